// round 1
// baseline (speedup 1.0000x reference)
#include <cuda_runtime.h>
#include <math.h>

#define B_   2
#define S_   2048
#define DM   1024
#define NH   16
#define DH   64
#define WIN  256
#define SCALEF 0.125f   // 1/sqrt(64)

// Scratch (allocation-free rule: __device__ globals)
__device__ float g_qkv[(size_t)B_ * S_ * 3 * DM];   // [B,S,3,H,Dh] row-major per token
__device__ float g_attn[(size_t)B_ * S_ * DM];      // [B,S,H*Dh]

// ---------------------------------------------------------------------------
// SGEMM: C[M,N] = A[M,K] @ B[K,N], all row-major fp32.
// 64x64 block tile, BK=16, 256 threads, 4x4 microtile.
// ---------------------------------------------------------------------------
__global__ __launch_bounds__(256) void sgemm64(
    const float* __restrict__ A, const float* __restrict__ Bm,
    float* __restrict__ C, int M, int N, int K)
{
    __shared__ float As[16][65];   // [k][m], padded to kill store conflicts
    __shared__ float Bs[16][64];   // [k][n]

    const int tx = threadIdx.x & 15;
    const int ty = threadIdx.x >> 4;
    const int row0 = blockIdx.y * 64;
    const int col0 = blockIdx.x * 64;

    float acc[4][4];
#pragma unroll
    for (int i = 0; i < 4; i++)
#pragma unroll
        for (int j = 0; j < 4; j++) acc[i][j] = 0.f;

    for (int k0 = 0; k0 < K; k0 += 16) {
#pragma unroll
        for (int u = 0; u < 4; u++) {
            int idx = threadIdx.x + u * 256;
            int r = idx >> 4, c = idx & 15;
            As[c][r] = A[(size_t)(row0 + r) * K + k0 + c];
            int rb = idx >> 6, cb = idx & 63;
            Bs[rb][cb] = Bm[(size_t)(k0 + rb) * N + col0 + cb];
        }
        __syncthreads();
#pragma unroll
        for (int k = 0; k < 16; k++) {
            float a[4], b[4];
#pragma unroll
            for (int i = 0; i < 4; i++) a[i] = As[k][ty * 4 + i];
#pragma unroll
            for (int j = 0; j < 4; j++) b[j] = Bs[k][tx * 4 + j];
#pragma unroll
            for (int i = 0; i < 4; i++)
#pragma unroll
                for (int j = 0; j < 4; j++) acc[i][j] += a[i] * b[j];
        }
        __syncthreads();
    }
#pragma unroll
    for (int i = 0; i < 4; i++)
#pragma unroll
        for (int j = 0; j < 4; j++)
            C[(size_t)(row0 + ty * 4 + i) * N + col0 + tx * 4 + j] = acc[i][j];
}

// ---------------------------------------------------------------------------
// Sliding-window flash attention.
// grid: (S/64, B*NH), block: 128 threads.
// Each block: one (b,h), 64 queries. Streams 64-key tiles with online softmax.
// qkv layout per token: [q(1024) | k(1024) | v(1024)], head h at offset h*64.
// ---------------------------------------------------------------------------
#define TPAD 68

__global__ __launch_bounds__(128) void attn_kernel(
    const float* __restrict__ qkv, float* __restrict__ out)
{
    extern __shared__ float sm[];
    float (*Q)[TPAD]  = (float(*)[TPAD])sm;
    float (*Kt)[TPAD] = (float(*)[TPAD])(sm + 64 * TPAD);
    float (*Vt)[TPAD] = (float(*)[TPAD])(sm + 2 * 64 * TPAD);
    float (*Sc)[TPAD] = (float(*)[TPAD])(sm + 3 * 64 * TPAD);
    float* mrow  = sm + 4 * 64 * TPAD;
    float* lrow  = mrow + 64;
    float* rsrow = lrow + 64;

    const int t  = threadIdx.x;
    const int qt = blockIdx.x;
    const int bh = blockIdx.y;
    const int b  = bh >> 4;
    const int h  = bh & 15;
    const int qs = qt * 64;
    const size_t tokStride = 3 * DM;

    // Load + pre-scale Q tile [64 x 64]
    const float* qbase = qkv + ((size_t)(b * S_ + qs)) * tokStride + h * DH;
    for (int idx = t; idx < 64 * 16; idx += 128) {
        int r = idx >> 4, c4 = (idx & 15) * 4;
        float4 v = *(const float4*)(qbase + (size_t)r * tokStride + c4);
        Q[r][c4 + 0] = v.x * SCALEF;
        Q[r][c4 + 1] = v.y * SCALEF;
        Q[r][c4 + 2] = v.z * SCALEF;
        Q[r][c4 + 3] = v.w * SCALEF;
    }
    if (t < 64) { mrow[t] = -INFINITY; lrow[t] = 0.f; }

    const int r  = t >> 1;        // query row owned (0..63), shared by 2 threads
    const int kh = (t & 1) * 32;  // key half for score phase
    const int dh = (t & 1) * 32;  // dim half for PV phase
    const int iglob = qs + r;

    float acc[32];
#pragma unroll
    for (int i = 0; i < 32; i++) acc[i] = 0.f;

    int js = qs - (WIN - 1);
    int t0 = js > 0 ? (js >> 6) : 0;

    for (int kt = t0; kt <= qt; kt++) {
        const int jb = kt * 64;
        __syncthreads();  // prior tile's Sc/Vt reads done before overwrite

        const float* kb = qkv + ((size_t)(b * S_ + jb)) * tokStride + DM + h * DH;
        const float* vb = kb + DM;
        for (int idx = t; idx < 64 * 16; idx += 128) {
            int rr = idx >> 4, c4 = (idx & 15) * 4;
            float4 kv = *(const float4*)(kb + (size_t)rr * tokStride + c4);
            Kt[rr][c4 + 0] = kv.x; Kt[rr][c4 + 1] = kv.y;
            Kt[rr][c4 + 2] = kv.z; Kt[rr][c4 + 3] = kv.w;
            float4 vv = *(const float4*)(vb + (size_t)rr * tokStride + c4);
            Vt[rr][c4 + 0] = vv.x; Vt[rr][c4 + 1] = vv.y;
            Vt[rr][c4 + 2] = vv.z; Vt[rr][c4 + 3] = vv.w;
        }
        __syncthreads();

        // ---- scores: this thread computes Sc[r][kh .. kh+31] ----
        float s[32];
#pragma unroll
        for (int i = 0; i < 32; i++) s[i] = 0.f;
        for (int d4 = 0; d4 < 64; d4 += 4) {
            float4 q4 = *(const float4*)&Q[r][d4];
#pragma unroll
            for (int kk = 0; kk < 32; kk++) {
                float4 k4 = *(const float4*)&Kt[kh + kk][d4];
                s[kk] += q4.x * k4.x + q4.y * k4.y + q4.z * k4.z + q4.w * k4.w;
            }
        }
#pragma unroll
        for (int kk = 0; kk < 32; kk++) {
            int j = jb + kh + kk;
            bool valid = (j <= iglob) && (j > iglob - WIN);
            Sc[r][kh + kk] = valid ? s[kk] : -INFINITY;
        }
        __syncthreads();

        // ---- online softmax row update (threads 0..63 own one row each) ----
        if (t < 64) {
            float mold = mrow[t];
            float mx = mold;
#pragma unroll 8
            for (int k = 0; k < 64; k++) mx = fmaxf(mx, Sc[t][k]);
            float resc;
            if (mx == -INFINITY) {
                resc = 1.f;
                for (int k = 0; k < 64; k++) Sc[t][k] = 0.f;
            } else {
                resc = __expf(mold - mx);   // mold=-inf -> 0
                float sum = 0.f;
                for (int k = 0; k < 64; k++) {
                    float p = __expf(Sc[t][k] - mx);  // -inf -> 0
                    Sc[t][k] = p;
                    sum += p;
                }
                lrow[t] = lrow[t] * resc + sum;
                mrow[t] = mx;
            }
            rsrow[t] = resc;
        }
        __syncthreads();

        // ---- PV: acc[dh..dh+31] += P[r][:] @ V[:, dh..dh+31] ----
        float re = rsrow[r];
#pragma unroll
        for (int i = 0; i < 32; i++) acc[i] *= re;
        for (int kk = 0; kk < 64; kk++) {
            float p = Sc[r][kk];
#pragma unroll
            for (int i4 = 0; i4 < 32; i4 += 4) {
                float4 v4 = *(const float4*)&Vt[kk][dh + i4];
                acc[i4 + 0] += p * v4.x;
                acc[i4 + 1] += p * v4.y;
                acc[i4 + 2] += p * v4.z;
                acc[i4 + 3] += p * v4.w;
            }
        }
    }

    float invl = 1.f / lrow[r];
    float* op = out + ((size_t)(b * S_ + qs + r)) * DM + h * DH + dh;
#pragma unroll
    for (int i = 0; i < 32; i++) op[i] = acc[i] * invl;
}

// ---------------------------------------------------------------------------
extern "C" void kernel_launch(void* const* d_in, const int* in_sizes, int n_in,
                              void* d_out, int out_size)
{
    const float* x    = (const float*)d_in[0];
    const float* Wqkv = (const float*)d_in[1];
    const float* Wout = (const float*)d_in[2];
    float* out = (float*)d_out;

    float *qkv_p, *attn_p;
    cudaGetSymbolAddress((void**)&qkv_p, g_qkv);
    cudaGetSymbolAddress((void**)&attn_p, g_attn);

    const int attn_smem = (4 * 64 * TPAD + 3 * 64) * (int)sizeof(float);  // ~70.4 KB
    cudaFuncSetAttribute(attn_kernel, cudaFuncAttributeMaxDynamicSharedMemorySize, attn_smem);

    // 1) QKV projection: [4096,1024] @ [1024,3072]
    sgemm64<<<dim3(3 * DM / 64, B_ * S_ / 64), 256>>>(x, Wqkv, qkv_p, B_ * S_, 3 * DM, DM);

    // 2) Sliding-window attention
    attn_kernel<<<dim3(S_ / 64, B_ * NH), 128, attn_smem>>>(qkv_p, attn_p);

    // 3) Output projection: [4096,1024] @ [1024,1024]
    sgemm64<<<dim3(DM / 64, B_ * S_ / 64), 256>>>(attn_p, Wout, out, B_ * S_, DM, DM);
}

// round 3
// speedup vs baseline: 1.6291x; 1.6291x over previous
#include <cuda_runtime.h>
#include <cuda_bf16.h>
#include <math.h>
#include <stdint.h>

#define B_   2
#define S_   2048
#define DM   1024
#define NH   16
#define DH   64
#define WIN  256
#define SCALEF 0.125f
#define MT   (B_*S_)

// ---------------- scratch (__device__ globals; no allocs allowed) ----------
__device__ float g_qkv[(size_t)MT * 3 * DM];
__device__ float g_attn[(size_t)MT * DM];
__device__ __nv_bfloat16 g_xh[(size_t)MT * DM],  g_xl[(size_t)MT * DM];
__device__ __nv_bfloat16 g_wqT_h[(size_t)3*DM*DM], g_wqT_l[(size_t)3*DM*DM];
__device__ __nv_bfloat16 g_woT_h[(size_t)DM*DM],   g_woT_l[(size_t)DM*DM];
__device__ __nv_bfloat16 g_ah[(size_t)MT*DM],  g_al[(size_t)MT*DM];

// ---------------- helpers ---------------------------------------------------
__device__ __forceinline__ uint32_t s2u(const void* p){
    uint32_t a;
    asm("{ .reg .u64 t; cvta.to.shared.u64 t, %1; cvt.u32.u64 %0, t; }":"=r"(a):"l"(p));
    return a;
}
__device__ __forceinline__ void cp16(uint32_t dst, const void* src){
    asm volatile("cp.async.cg.shared.global [%0], [%1], 16;"::"r"(dst),"l"(src));
}
__device__ __forceinline__ void ldsm_x4(uint32_t& r0,uint32_t& r1,uint32_t& r2,uint32_t& r3,uint32_t addr){
    asm volatile("ldmatrix.sync.aligned.m8n8.x4.shared.b16 {%0,%1,%2,%3}, [%4];"
        : "=r"(r0),"=r"(r1),"=r"(r2),"=r"(r3) : "r"(addr));
}
__device__ __forceinline__ void mma16816(float* c, uint32_t a0,uint32_t a1,uint32_t a2,uint32_t a3,
                                         uint32_t b0,uint32_t b1){
    asm volatile("mma.sync.aligned.m16n8k16.row.col.f32.bf16.bf16.f32 "
        "{%0,%1,%2,%3}, {%4,%5,%6,%7}, {%8,%9}, {%0,%1,%2,%3};"
        : "+f"(c[0]),"+f"(c[1]),"+f"(c[2]),"+f"(c[3])
        : "r"(a0),"r"(a1),"r"(a2),"r"(a3),"r"(b0),"r"(b1));
}

// ---------------- prep kernels ---------------------------------------------
__global__ __launch_bounds__(256) void fsplit(const float* __restrict__ in,
                                              __nv_bfloat16* __restrict__ hi,
                                              __nv_bfloat16* __restrict__ lo, int n)
{
    int i = (blockIdx.x*256 + threadIdx.x)*2;
    if (i >= n) return;
    float2 v = *(const float2*)(in + i);
    __nv_bfloat16 h0 = __float2bfloat16(v.x);
    __nv_bfloat16 h1 = __float2bfloat16(v.y);
    float l0 = v.x - __bfloat162float(h0);
    float l1 = v.y - __bfloat162float(h1);
    *(__nv_bfloat162*)(hi + i) = __halves2bfloat162(h0, h1);
    *(__nv_bfloat162*)(lo + i) = __halves2bfloat162(__float2bfloat16(l0), __float2bfloat16(l1));
}

// W [K,N] row-major -> transposed split Th/Tl [N,K] bf16
__global__ __launch_bounds__(256) void tsplit(const float* __restrict__ W,
                                              __nv_bfloat16* __restrict__ Th,
                                              __nv_bfloat16* __restrict__ Tl, int K, int N)
{
    __shared__ float t[32][33];
    int n0 = blockIdx.x*32, k0 = blockIdx.y*32;
    int tx = threadIdx.x & 31, ty = threadIdx.x >> 5;  // 32x8
#pragma unroll
    for (int i = 0; i < 32; i += 8)
        t[ty+i][tx] = W[(size_t)(k0+ty+i)*N + n0+tx];
    __syncthreads();
#pragma unroll
    for (int i = 0; i < 32; i += 8){
        float v = t[tx][ty+i];
        __nv_bfloat16 h = __float2bfloat16(v);
        float lo = v - __bfloat162float(h);
        size_t o = (size_t)(n0+ty+i)*K + k0+tx;
        Th[o] = h; Tl[o] = __float2bfloat16(lo);
    }
}

// ---------------- bf16x3 HMMA GEMM ------------------------------------------
// C[M,N] = Ah@Bh^T + Ah@Bl^T + Al@Bh^T   (A [M,K] bf16, B [N,K] bf16, C fp32)
#define BM 128
#define BN 128
#define BK 32
#define STAGES 3
#define ROWB 80                        // smem row stride bytes (40 bf16) — ldmatrix conflict-free
#define HALF_BYTES (128*ROWB)          // 10240
#define GSTAGE_BYTES (4*HALF_BYTES)    // 40960
#define OFF_AH 0
#define OFF_AL HALF_BYTES
#define OFF_BH (2*HALF_BYTES)
#define OFF_BL (3*HALF_BYTES)
#define GEMM_SMEM (STAGES*GSTAGE_BYTES)

__global__ __launch_bounds__(256, 1) void gemm_bf16x3(
    const __nv_bfloat16* __restrict__ Ah, const __nv_bfloat16* __restrict__ Al,
    const __nv_bfloat16* __restrict__ Bh, const __nv_bfloat16* __restrict__ Bl,
    float* __restrict__ C, int M, int N, int K)
{
    extern __shared__ char smraw[];
    const uint32_t sb = s2u(smraw);
    const int tid = threadIdx.x, lane = tid & 31, wid = tid >> 5;
    const int row0 = blockIdx.y * BM, col0 = blockIdx.x * BN;
    const int wm = (wid & 1) * 64;   // warp row offset
    const int wn = (wid >> 1) * 32;  // warp col offset
    const int nch = K / BK;

    const __nv_bfloat16* pAh = Ah + (size_t)row0 * K;
    const __nv_bfloat16* pAl = Al + (size_t)row0 * K;
    const __nv_bfloat16* pBh = Bh + (size_t)col0 * K;
    const __nv_bfloat16* pBl = Bl + (size_t)col0 * K;

    const int lr = tid >> 2;            // 0..63 (+64 with u)
    const int lq = tid & 3;             // 16B chunk within 64B row-slab

    float acc[4][4][4];
#pragma unroll
    for (int f = 0; f < 4; f++)
#pragma unroll
        for (int j = 0; j < 4; j++)
#pragma unroll
            for (int i = 0; i < 4; i++) acc[f][j][i] = 0.f;

#define LOAD_STAGE(s_, c_)                                              \
    {                                                                   \
        uint32_t base_ = sb + (s_) * GSTAGE_BYTES;                      \
        size_t kof_ = (size_t)(c_) * BK;                                \
        _Pragma("unroll")                                               \
        for (int u = 0; u < 2; u++){                                    \
            int r_ = lr + u * 64;                                       \
            uint32_t d_ = base_ + r_ * ROWB + lq * 16;                  \
            size_t g_ = (size_t)r_ * K + kof_ + lq * 8;                 \
            cp16(d_ + OFF_AH, pAh + g_);                                \
            cp16(d_ + OFF_AL, pAl + g_);                                \
            cp16(d_ + OFF_BH, pBh + g_);                                \
            cp16(d_ + OFF_BL, pBl + g_);                                \
        }                                                               \
    }

    // prologue
#pragma unroll
    for (int p = 0; p < STAGES - 1; p++){
        LOAD_STAGE(p, p);
        asm volatile("cp.async.commit_group;");
    }

    for (int c = 0; c < nch; c++){
        const int pre = c + STAGES - 1;
        if (pre < nch) LOAD_STAGE(pre % STAGES, pre);
        asm volatile("cp.async.commit_group;");
        asm volatile("cp.async.wait_group %0;"::"n"(STAGES - 2));
        __syncthreads();

        const uint32_t base = sb + (c % STAGES) * GSTAGE_BYTES;
#pragma unroll
        for (int ks = 0; ks < 2; ks++){
            const uint32_t kcol = (ks * 16 + (lane >> 4) * 8) * 2;
            uint32_t ah[4][4], al[4][4], bh[2][4], bl[2][4];
#pragma unroll
            for (int f = 0; f < 4; f++){
                uint32_t ad = (wm + f * 16 + (lane & 15)) * ROWB + kcol;
                ldsm_x4(ah[f][0], ah[f][1], ah[f][2], ah[f][3], base + OFF_AH + ad);
                ldsm_x4(al[f][0], al[f][1], al[f][2], al[f][3], base + OFF_AL + ad);
            }
#pragma unroll
            for (int g = 0; g < 2; g++){
                uint32_t bd = (wn + g * 16 + (lane & 15)) * ROWB + kcol;
                ldsm_x4(bh[g][0], bh[g][1], bh[g][2], bh[g][3], base + OFF_BH + bd);
                ldsm_x4(bl[g][0], bl[g][1], bl[g][2], bl[g][3], base + OFF_BL + bd);
            }
#pragma unroll
            for (int f = 0; f < 4; f++)
#pragma unroll
                for (int j = 0; j < 4; j++){
                    const int g = j >> 1, o = j & 1;
                    mma16816(acc[f][j], ah[f][0], ah[f][1], ah[f][2], ah[f][3],
                             bh[g][o], bh[g][o + 2]);
                    mma16816(acc[f][j], ah[f][0], ah[f][1], ah[f][2], ah[f][3],
                             bl[g][o], bl[g][o + 2]);
                    mma16816(acc[f][j], al[f][0], al[f][1], al[f][2], al[f][3],
                             bh[g][o], bh[g][o + 2]);
                }
        }
        __syncthreads();
    }

    // epilogue: fragment -> gmem
#pragma unroll
    for (int f = 0; f < 4; f++){
        const int row = row0 + wm + f * 16 + (lane >> 2);
#pragma unroll
        for (int j = 0; j < 4; j++){
            const int col = col0 + wn + j * 8 + (lane & 3) * 2;
            float2 v0 = make_float2(acc[f][j][0], acc[f][j][1]);
            float2 v1 = make_float2(acc[f][j][2], acc[f][j][3]);
            *(float2*)(C + (size_t)row * N + col)       = v0;
            *(float2*)(C + (size_t)(row + 8) * N + col) = v1;
        }
    }
}

// ---------------- sliding-window flash attention (unchanged) ----------------
#define TPAD 68

__global__ __launch_bounds__(128) void attn_kernel(
    const float* __restrict__ qkv, float* __restrict__ out)
{
    extern __shared__ float sm[];
    float (*Q)[TPAD]  = (float(*)[TPAD])sm;
    float (*Kt)[TPAD] = (float(*)[TPAD])(sm + 64 * TPAD);
    float (*Vt)[TPAD] = (float(*)[TPAD])(sm + 2 * 64 * TPAD);
    float (*Sc)[TPAD] = (float(*)[TPAD])(sm + 3 * 64 * TPAD);
    float* mrow  = sm + 4 * 64 * TPAD;
    float* lrow  = mrow + 64;
    float* rsrow = lrow + 64;

    const int t  = threadIdx.x;
    const int qt = blockIdx.x;
    const int bh = blockIdx.y;
    const int b  = bh >> 4;
    const int h  = bh & 15;
    const int qs = qt * 64;
    const size_t tokStride = 3 * DM;

    const float* qbase = qkv + ((size_t)(b * S_ + qs)) * tokStride + h * DH;
    for (int idx = t; idx < 64 * 16; idx += 128) {
        int r = idx >> 4, c4 = (idx & 15) * 4;
        float4 v = *(const float4*)(qbase + (size_t)r * tokStride + c4);
        Q[r][c4 + 0] = v.x * SCALEF;
        Q[r][c4 + 1] = v.y * SCALEF;
        Q[r][c4 + 2] = v.z * SCALEF;
        Q[r][c4 + 3] = v.w * SCALEF;
    }
    if (t < 64) { mrow[t] = -INFINITY; lrow[t] = 0.f; }

    const int r  = t >> 1;
    const int kh = (t & 1) * 32;
    const int dh = (t & 1) * 32;
    const int iglob = qs + r;

    float acc[32];
#pragma unroll
    for (int i = 0; i < 32; i++) acc[i] = 0.f;

    int js = qs - (WIN - 1);
    int t0 = js > 0 ? (js >> 6) : 0;

    for (int kt = t0; kt <= qt; kt++) {
        const int jb = kt * 64;
        __syncthreads();

        const float* kb = qkv + ((size_t)(b * S_ + jb)) * tokStride + DM + h * DH;
        const float* vb = kb + DM;
        for (int idx = t; idx < 64 * 16; idx += 128) {
            int rr = idx >> 4, c4 = (idx & 15) * 4;
            float4 kv = *(const float4*)(kb + (size_t)rr * tokStride + c4);
            Kt[rr][c4 + 0] = kv.x; Kt[rr][c4 + 1] = kv.y;
            Kt[rr][c4 + 2] = kv.z; Kt[rr][c4 + 3] = kv.w;
            float4 vv = *(const float4*)(vb + (size_t)rr * tokStride + c4);
            Vt[rr][c4 + 0] = vv.x; Vt[rr][c4 + 1] = vv.y;
            Vt[rr][c4 + 2] = vv.z; Vt[rr][c4 + 3] = vv.w;
        }
        __syncthreads();

        float s[32];
#pragma unroll
        for (int i = 0; i < 32; i++) s[i] = 0.f;
        for (int d4 = 0; d4 < 64; d4 += 4) {
            float4 q4 = *(const float4*)&Q[r][d4];
#pragma unroll
            for (int kk = 0; kk < 32; kk++) {
                float4 k4 = *(const float4*)&Kt[kh + kk][d4];
                s[kk] += q4.x * k4.x + q4.y * k4.y + q4.z * k4.z + q4.w * k4.w;
            }
        }
#pragma unroll
        for (int kk = 0; kk < 32; kk++) {
            int j = jb + kh + kk;
            bool valid = (j <= iglob) && (j > iglob - WIN);
            Sc[r][kh + kk] = valid ? s[kk] : -INFINITY;
        }
        __syncthreads();

        if (t < 64) {
            float mold = mrow[t];
            float mx = mold;
#pragma unroll 8
            for (int k = 0; k < 64; k++) mx = fmaxf(mx, Sc[t][k]);
            float resc;
            if (mx == -INFINITY) {
                resc = 1.f;
                for (int k = 0; k < 64; k++) Sc[t][k] = 0.f;
            } else {
                resc = __expf(mold - mx);
                float sum = 0.f;
                for (int k = 0; k < 64; k++) {
                    float p = __expf(Sc[t][k] - mx);
                    Sc[t][k] = p;
                    sum += p;
                }
                lrow[t] = lrow[t] * resc + sum;
                mrow[t] = mx;
            }
            rsrow[t] = resc;
        }
        __syncthreads();

        float re = rsrow[r];
#pragma unroll
        for (int i = 0; i < 32; i++) acc[i] *= re;
        for (int kk = 0; kk < 64; kk++) {
            float p = Sc[r][kk];
#pragma unroll
            for (int i4 = 0; i4 < 32; i4 += 4) {
                float4 v4 = *(const float4*)&Vt[kk][dh + i4];
                acc[i4 + 0] += p * v4.x;
                acc[i4 + 1] += p * v4.y;
                acc[i4 + 2] += p * v4.z;
                acc[i4 + 3] += p * v4.w;
            }
        }
    }

    float invl = 1.f / lrow[r];
    float* op = out + ((size_t)(b * S_ + qs + r)) * DM + h * DH + dh;
#pragma unroll
    for (int i = 0; i < 32; i++) op[i] = acc[i] * invl;
}

// ---------------------------------------------------------------------------
extern "C" void kernel_launch(void* const* d_in, const int* in_sizes, int n_in,
                              void* d_out, int out_size)
{
    const float* x    = (const float*)d_in[0];
    const float* Wqkv = (const float*)d_in[1];
    const float* Wout = (const float*)d_in[2];
    float* out = (float*)d_out;

    float *qkv_p, *attn_p;
    __nv_bfloat16 *xh, *xl, *wqh, *wql, *woh, *wol, *ah, *al;
    cudaGetSymbolAddress((void**)&qkv_p, g_qkv);
    cudaGetSymbolAddress((void**)&attn_p, g_attn);
    cudaGetSymbolAddress((void**)&xh, g_xh);
    cudaGetSymbolAddress((void**)&xl, g_xl);
    cudaGetSymbolAddress((void**)&wqh, g_wqT_h);
    cudaGetSymbolAddress((void**)&wql, g_wqT_l);
    cudaGetSymbolAddress((void**)&woh, g_woT_h);
    cudaGetSymbolAddress((void**)&wol, g_woT_l);
    cudaGetSymbolAddress((void**)&ah, g_ah);
    cudaGetSymbolAddress((void**)&al, g_al);

    const int attn_smem = (4 * 64 * TPAD + 3 * 64) * (int)sizeof(float);
    cudaFuncSetAttribute(attn_kernel, cudaFuncAttributeMaxDynamicSharedMemorySize, attn_smem);
    cudaFuncSetAttribute(gemm_bf16x3, cudaFuncAttributeMaxDynamicSharedMemorySize, GEMM_SMEM);

    // 1) split x into bf16 hi/lo
    fsplit<<<(MT*DM/2 + 255)/256, 256>>>(x, xh, xl, MT*DM);
    // 2) transpose + split weights
    tsplit<<<dim3(3*DM/32, DM/32), 256>>>(Wqkv, wqh, wql, DM, 3*DM);
    tsplit<<<dim3(DM/32, DM/32), 256>>>(Wout, woh, wol, DM, DM);
    // 3) QKV projection (HMMA bf16x3): [4096,1024] x [3072,1024]^T
    gemm_bf16x3<<<dim3(3*DM/BN, MT/BM), 256, GEMM_SMEM>>>(xh, xl, wqh, wql, qkv_p, MT, 3*DM, DM);
    // 4) sliding-window attention
    attn_kernel<<<dim3(S_/64, B_*NH), 128, attn_smem>>>(qkv_p, attn_p);
    // 5) split attention output
    fsplit<<<(MT*DM/2 + 255)/256, 256>>>(attn_p, ah, al, MT*DM);
    // 6) output projection
    gemm_bf16x3<<<dim3(DM/BN, MT/BM), 256, GEMM_SMEM>>>(ah, al, woh, wol, out, MT, DM, DM);
}

// round 4
// speedup vs baseline: 2.4884x; 1.5275x over previous
#include <cuda_runtime.h>
#include <cuda_bf16.h>
#include <math.h>
#include <stdint.h>

#define B_   2
#define S_   2048
#define DM   1024
#define NH   16
#define DH   64
#define WIN  256
#define SCALEF 0.125f
#define MT   (B_*S_)

// ---------------- scratch (__device__ globals; no allocs allowed) ----------
__device__ __nv_bfloat16 g_xh[(size_t)MT * DM],  g_xl[(size_t)MT * DM];
__device__ __nv_bfloat16 g_wqT_h[(size_t)3*DM*DM], g_wqT_l[(size_t)3*DM*DM];
__device__ __nv_bfloat16 g_woT_h[(size_t)DM*DM],   g_woT_l[(size_t)DM*DM];
__device__ __nv_bfloat16 g_qkvh[(size_t)MT*3*DM], g_qkvl[(size_t)MT*3*DM];
__device__ __nv_bfloat16 g_ah[(size_t)MT*DM],  g_al[(size_t)MT*DM];

// ---------------- helpers ---------------------------------------------------
__device__ __forceinline__ uint32_t s2u(const void* p){
    uint32_t a;
    asm("{ .reg .u64 t; cvta.to.shared.u64 t, %1; cvt.u32.u64 %0, t; }":"=r"(a):"l"(p));
    return a;
}
__device__ __forceinline__ void cp16(uint32_t dst, const void* src){
    asm volatile("cp.async.cg.shared.global [%0], [%1], 16;"::"r"(dst),"l"(src));
}
__device__ __forceinline__ void ldsm_x4(uint32_t& r0,uint32_t& r1,uint32_t& r2,uint32_t& r3,uint32_t addr){
    asm volatile("ldmatrix.sync.aligned.m8n8.x4.shared.b16 {%0,%1,%2,%3}, [%4];"
        : "=r"(r0),"=r"(r1),"=r"(r2),"=r"(r3) : "r"(addr));
}
__device__ __forceinline__ void ldsm_x4t(uint32_t& r0,uint32_t& r1,uint32_t& r2,uint32_t& r3,uint32_t addr){
    asm volatile("ldmatrix.sync.aligned.m8n8.x4.trans.shared.b16 {%0,%1,%2,%3}, [%4];"
        : "=r"(r0),"=r"(r1),"=r"(r2),"=r"(r3) : "r"(addr));
}
__device__ __forceinline__ void mma16816(float* c, uint32_t a0,uint32_t a1,uint32_t a2,uint32_t a3,
                                         uint32_t b0,uint32_t b1){
    asm volatile("mma.sync.aligned.m16n8k16.row.col.f32.bf16.bf16.f32 "
        "{%0,%1,%2,%3}, {%4,%5,%6,%7}, {%8,%9}, {%0,%1,%2,%3};"
        : "+f"(c[0]),"+f"(c[1]),"+f"(c[2]),"+f"(c[3])
        : "r"(a0),"r"(a1),"r"(a2),"r"(a3),"r"(b0),"r"(b1));
}
__device__ __forceinline__ uint32_t packsplit(float x, float y, uint32_t& lo){
    __nv_bfloat16 hx = __float2bfloat16(x), hy = __float2bfloat16(y);
    __nv_bfloat16 lx = __float2bfloat16(x - __bfloat162float(hx));
    __nv_bfloat16 ly = __float2bfloat16(y - __bfloat162float(hy));
    lo = (uint32_t)__bfloat16_as_ushort(lx) | ((uint32_t)__bfloat16_as_ushort(ly)<<16);
    return (uint32_t)__bfloat16_as_ushort(hx) | ((uint32_t)__bfloat16_as_ushort(hy)<<16);
}

// ---------------- prep kernels ---------------------------------------------
__global__ __launch_bounds__(256) void fsplit(const float* __restrict__ in,
                                              __nv_bfloat16* __restrict__ hi,
                                              __nv_bfloat16* __restrict__ lo, int n)
{
    int i = (blockIdx.x*256 + threadIdx.x)*2;
    if (i >= n) return;
    float2 v = *(const float2*)(in + i);
    __nv_bfloat16 h0 = __float2bfloat16(v.x);
    __nv_bfloat16 h1 = __float2bfloat16(v.y);
    float l0 = v.x - __bfloat162float(h0);
    float l1 = v.y - __bfloat162float(h1);
    *(__nv_bfloat162*)(hi + i) = __halves2bfloat162(h0, h1);
    *(__nv_bfloat162*)(lo + i) = __halves2bfloat162(__float2bfloat16(l0), __float2bfloat16(l1));
}

// W [K,N] row-major -> transposed split Th/Tl [N,K] bf16
__global__ __launch_bounds__(256) void tsplit(const float* __restrict__ W,
                                              __nv_bfloat16* __restrict__ Th,
                                              __nv_bfloat16* __restrict__ Tl, int K, int N)
{
    __shared__ float t[32][33];
    int n0 = blockIdx.x*32, k0 = blockIdx.y*32;
    int tx = threadIdx.x & 31, ty = threadIdx.x >> 5;  // 32x8
#pragma unroll
    for (int i = 0; i < 32; i += 8)
        t[ty+i][tx] = W[(size_t)(k0+ty+i)*N + n0+tx];
    __syncthreads();
#pragma unroll
    for (int i = 0; i < 32; i += 8){
        float v = t[tx][ty+i];
        __nv_bfloat16 h = __float2bfloat16(v);
        float lo = v - __bfloat162float(h);
        size_t o = (size_t)(n0+ty+i)*K + k0+tx;
        Th[o] = h; Tl[o] = __float2bfloat16(lo);
    }
}

// ---------------- bf16x3 HMMA GEMM ------------------------------------------
// C = Ah@Bh^T + Ah@Bl^T + Al@Bh^T.  Output: split bf16 (Ch,Cl) or fp32 (Cf).
#define BM 128
#define BN 128
#define BK 32
#define STAGES 3
#define ROWB 80
#define HALF_BYTES (128*ROWB)
#define GSTAGE_BYTES (4*HALF_BYTES)
#define OFF_AH 0
#define OFF_AL HALF_BYTES
#define OFF_BH (2*HALF_BYTES)
#define OFF_BL (3*HALF_BYTES)
#define GEMM_SMEM (STAGES*GSTAGE_BYTES)

__global__ __launch_bounds__(256, 1) void gemm_bf16x3(
    const __nv_bfloat16* __restrict__ Ah, const __nv_bfloat16* __restrict__ Al,
    const __nv_bfloat16* __restrict__ Bh, const __nv_bfloat16* __restrict__ Bl,
    __nv_bfloat16* __restrict__ Ch, __nv_bfloat16* __restrict__ Cl,
    float* __restrict__ Cf, int M, int N, int K)
{
    extern __shared__ char smraw[];
    const uint32_t sb = s2u(smraw);
    const int tid = threadIdx.x, lane = tid & 31, wid = tid >> 5;
    const int row0 = blockIdx.y * BM, col0 = blockIdx.x * BN;
    const int wm = (wid & 1) * 64;
    const int wn = (wid >> 1) * 32;
    const int nch = K / BK;

    const __nv_bfloat16* pAh = Ah + (size_t)row0 * K;
    const __nv_bfloat16* pAl = Al + (size_t)row0 * K;
    const __nv_bfloat16* pBh = Bh + (size_t)col0 * K;
    const __nv_bfloat16* pBl = Bl + (size_t)col0 * K;

    const int lr = tid >> 2;
    const int lq = tid & 3;

    float acc[4][4][4];
#pragma unroll
    for (int f = 0; f < 4; f++)
#pragma unroll
        for (int j = 0; j < 4; j++)
#pragma unroll
            for (int i = 0; i < 4; i++) acc[f][j][i] = 0.f;

#define LOAD_STAGE(s_, c_)                                              \
    {                                                                   \
        uint32_t base_ = sb + (s_) * GSTAGE_BYTES;                      \
        size_t kof_ = (size_t)(c_) * BK;                                \
        _Pragma("unroll")                                               \
        for (int u = 0; u < 2; u++){                                    \
            int r_ = lr + u * 64;                                       \
            uint32_t d_ = base_ + r_ * ROWB + lq * 16;                  \
            size_t g_ = (size_t)r_ * K + kof_ + lq * 8;                 \
            cp16(d_ + OFF_AH, pAh + g_);                                \
            cp16(d_ + OFF_AL, pAl + g_);                                \
            cp16(d_ + OFF_BH, pBh + g_);                                \
            cp16(d_ + OFF_BL, pBl + g_);                                \
        }                                                               \
    }

#pragma unroll
    for (int p = 0; p < STAGES - 1; p++){
        LOAD_STAGE(p, p);
        asm volatile("cp.async.commit_group;");
    }

    for (int c = 0; c < nch; c++){
        const int pre = c + STAGES - 1;
        if (pre < nch) LOAD_STAGE(pre % STAGES, pre);
        asm volatile("cp.async.commit_group;");
        asm volatile("cp.async.wait_group %0;"::"n"(STAGES - 2));
        __syncthreads();

        const uint32_t base = sb + (c % STAGES) * GSTAGE_BYTES;
#pragma unroll
        for (int ks = 0; ks < 2; ks++){
            const uint32_t kcol = (ks * 16 + (lane >> 4) * 8) * 2;
            uint32_t ah[4][4], al[4][4], bh[2][4], bl[2][4];
#pragma unroll
            for (int f = 0; f < 4; f++){
                uint32_t ad = (wm + f * 16 + (lane & 15)) * ROWB + kcol;
                ldsm_x4(ah[f][0], ah[f][1], ah[f][2], ah[f][3], base + OFF_AH + ad);
                ldsm_x4(al[f][0], al[f][1], al[f][2], al[f][3], base + OFF_AL + ad);
            }
#pragma unroll
            for (int g = 0; g < 2; g++){
                uint32_t bd = (wn + g * 16 + (lane & 15)) * ROWB + kcol;
                ldsm_x4(bh[g][0], bh[g][1], bh[g][2], bh[g][3], base + OFF_BH + bd);
                ldsm_x4(bl[g][0], bl[g][1], bl[g][2], bl[g][3], base + OFF_BL + bd);
            }
#pragma unroll
            for (int f = 0; f < 4; f++)
#pragma unroll
                for (int j = 0; j < 4; j++){
                    const int g = j >> 1, o = j & 1;
                    mma16816(acc[f][j], ah[f][0], ah[f][1], ah[f][2], ah[f][3],
                             bh[g][o], bh[g][o + 2]);
                    mma16816(acc[f][j], ah[f][0], ah[f][1], ah[f][2], ah[f][3],
                             bl[g][o], bl[g][o + 2]);
                    mma16816(acc[f][j], al[f][0], al[f][1], al[f][2], al[f][3],
                             bh[g][o], bh[g][o + 2]);
                }
        }
        __syncthreads();
    }

#pragma unroll
    for (int f = 0; f < 4; f++){
        const int row = row0 + wm + f * 16 + (lane >> 2);
#pragma unroll
        for (int j = 0; j < 4; j++){
            const int col = col0 + wn + j * 8 + (lane & 3) * 2;
            if (Cf){
                *(float2*)(Cf + (size_t)row * N + col)       = make_float2(acc[f][j][0], acc[f][j][1]);
                *(float2*)(Cf + (size_t)(row + 8) * N + col) = make_float2(acc[f][j][2], acc[f][j][3]);
            } else {
                uint32_t lo0, hi0, lo1, hi1;
                hi0 = packsplit(acc[f][j][0], acc[f][j][1], lo0);
                hi1 = packsplit(acc[f][j][2], acc[f][j][3], lo1);
                *(uint32_t*)(Ch + (size_t)row * N + col)       = hi0;
                *(uint32_t*)(Cl + (size_t)row * N + col)       = lo0;
                *(uint32_t*)(Ch + (size_t)(row + 8) * N + col) = hi1;
                *(uint32_t*)(Cl + (size_t)(row + 8) * N + col) = lo1;
            }
        }
    }
}

// ---------------- HMMA sliding-window flash attention -----------------------
// grid (S/64, B*NH), 128 threads = 4 warps; warp w owns q-rows 16w..16w+15.
// qkv split bf16 in, attention output split bf16 out.
#define RWB 144                 // smem row stride bytes (72 bf16)
#define BQH 0
#define BQL (64*RWB)
#define BKH (2*64*RWB)
#define BKL (3*64*RWB)
#define BVH (4*64*RWB)
#define BVL (5*64*RWB)
#define ATTN_SMEM (6*64*RWB)    // 55296 B

__global__ __launch_bounds__(128) void attn_hmma(
    const __nv_bfloat16* __restrict__ qh, const __nv_bfloat16* __restrict__ ql,
    __nv_bfloat16* __restrict__ oh, __nv_bfloat16* __restrict__ ol)
{
    extern __shared__ char smc[];
    const uint32_t sb = s2u(smc);
    const int tid = threadIdx.x, lane = tid & 31, wid = tid >> 5;
    const int qt = blockIdx.x, bhid = blockIdx.y;
    const int b = bhid >> 4, h = bhid & 15;
    const int qs = qt * 64;
    const int wm = wid * 16;
    const size_t tok0 = (size_t)b * S_;

    // ---- load Q tile hi/lo into smem ----
    {
        const __nv_bfloat16* qbh = qh + (tok0 + qs) * 3072 + h * 64;
        const __nv_bfloat16* qbl = ql + (tok0 + qs) * 3072 + h * 64;
        for (int i = tid; i < 512; i += 128){
            int r = i >> 3, q = i & 7;
            *(uint4*)(smc + BQH + r*RWB + q*16) = *(const uint4*)(qbh + (size_t)r*3072 + q*8);
            *(uint4*)(smc + BQL + r*RWB + q*16) = *(const uint4*)(qbl + (size_t)r*3072 + q*8);
        }
    }
    __syncthreads();

    // ---- persistent Q fragments ----
    uint32_t aqh[4][4], aql[4][4];
#pragma unroll
    for (int ks = 0; ks < 4; ks++){
        uint32_t ad = (uint32_t)((wm + (lane & 15)) * RWB + (ks*16 + (lane >> 4)*8) * 2);
        ldsm_x4(aqh[ks][0], aqh[ks][1], aqh[ks][2], aqh[ks][3], sb + BQH + ad);
        ldsm_x4(aql[ks][0], aql[ks][1], aql[ks][2], aql[ks][3], sb + BQL + ad);
    }

    float oacc[8][4];
#pragma unroll
    for (int f = 0; f < 8; f++)
#pragma unroll
        for (int e = 0; e < 4; e++) oacc[f][e] = 0.f;
    float m0 = -1e30f, m1 = -1e30f, l0 = 0.f, l1 = 0.f;

    const int ilo = qs + wm + (lane >> 2);
    const int ihi = ilo + 8;

    const int js = qs - (WIN - 1);
    const int t0 = js > 0 ? (js >> 6) : 0;

    for (int kt = t0; kt <= qt; kt++){
        const int jb = kt * 64;
        __syncthreads();   // prior tile reads done
        // ---- load K/V tiles hi/lo ----
        for (int i = tid; i < 512; i += 128){
            int r = i >> 3, q = i & 7;
            size_t g = (tok0 + jb + r) * 3072 + h*64 + q*8;
            uint32_t so = r*RWB + q*16;
            *(uint4*)(smc + BKH + so) = *(const uint4*)(qh + g + 1024);
            *(uint4*)(smc + BKL + so) = *(const uint4*)(ql + g + 1024);
            *(uint4*)(smc + BVH + so) = *(const uint4*)(qh + g + 2048);
            *(uint4*)(smc + BVL + so) = *(const uint4*)(ql + g + 2048);
        }
        __syncthreads();

        // ---- scores ----
        float sacc[8][4];
#pragma unroll
        for (int f = 0; f < 8; f++)
#pragma unroll
            for (int e = 0; e < 4; e++) sacc[f][e] = 0.f;

#pragma unroll
        for (int g = 0; g < 4; g++){
#pragma unroll
            for (int ks = 0; ks < 4; ks++){
                uint32_t bd = (uint32_t)((g*16 + (lane & 15)) * RWB + (ks*16 + (lane >> 4)*8) * 2);
                uint32_t kh0,kh1,kh2,kh3, kl0,kl1,kl2,kl3;
                ldsm_x4(kh0,kh1,kh2,kh3, sb + BKH + bd);
                ldsm_x4(kl0,kl1,kl2,kl3, sb + BKL + bd);
                mma16816(sacc[2*g],   aqh[ks][0],aqh[ks][1],aqh[ks][2],aqh[ks][3], kh0, kh2);
                mma16816(sacc[2*g],   aqh[ks][0],aqh[ks][1],aqh[ks][2],aqh[ks][3], kl0, kl2);
                mma16816(sacc[2*g],   aql[ks][0],aql[ks][1],aql[ks][2],aql[ks][3], kh0, kh2);
                mma16816(sacc[2*g+1], aqh[ks][0],aqh[ks][1],aqh[ks][2],aqh[ks][3], kh1, kh3);
                mma16816(sacc[2*g+1], aqh[ks][0],aqh[ks][1],aqh[ks][2],aqh[ks][3], kl1, kl3);
                mma16816(sacc[2*g+1], aql[ks][0],aql[ks][1],aql[ks][2],aql[ks][3], kh1, kh3);
            }
        }

        // ---- scale + mask + online softmax ----
        float mx0 = -1e30f, mx1 = -1e30f;
#pragma unroll
        for (int f = 0; f < 8; f++){
            int c0 = jb + f*8 + 2*(lane & 3);
            int c1 = c0 + 1;
            float s0 = sacc[f][0]*SCALEF, s1 = sacc[f][1]*SCALEF;
            float s2 = sacc[f][2]*SCALEF, s3 = sacc[f][3]*SCALEF;
            sacc[f][0] = (c0 <= ilo && c0 > ilo - WIN) ? s0 : -1e30f;
            sacc[f][1] = (c1 <= ilo && c1 > ilo - WIN) ? s1 : -1e30f;
            sacc[f][2] = (c0 <= ihi && c0 > ihi - WIN) ? s2 : -1e30f;
            sacc[f][3] = (c1 <= ihi && c1 > ihi - WIN) ? s3 : -1e30f;
            mx0 = fmaxf(mx0, fmaxf(sacc[f][0], sacc[f][1]));
            mx1 = fmaxf(mx1, fmaxf(sacc[f][2], sacc[f][3]));
        }
        mx0 = fmaxf(mx0, __shfl_xor_sync(0xffffffffu, mx0, 1));
        mx0 = fmaxf(mx0, __shfl_xor_sync(0xffffffffu, mx0, 2));
        mx1 = fmaxf(mx1, __shfl_xor_sync(0xffffffffu, mx1, 1));
        mx1 = fmaxf(mx1, __shfl_xor_sync(0xffffffffu, mx1, 2));
        float mn0 = fmaxf(m0, mx0), mn1 = fmaxf(m1, mx1);
        float rc0 = __expf(m0 - mn0), rc1 = __expf(m1 - mn1);
        float rs0 = 0.f, rs1 = 0.f;
#pragma unroll
        for (int f = 0; f < 8; f++){
            sacc[f][0] = __expf(sacc[f][0] - mn0);
            sacc[f][1] = __expf(sacc[f][1] - mn0);
            sacc[f][2] = __expf(sacc[f][2] - mn1);
            sacc[f][3] = __expf(sacc[f][3] - mn1);
            rs0 += sacc[f][0] + sacc[f][1];
            rs1 += sacc[f][2] + sacc[f][3];
        }
        rs0 += __shfl_xor_sync(0xffffffffu, rs0, 1);
        rs0 += __shfl_xor_sync(0xffffffffu, rs0, 2);
        rs1 += __shfl_xor_sync(0xffffffffu, rs1, 1);
        rs1 += __shfl_xor_sync(0xffffffffu, rs1, 2);
        l0 = l0 * rc0 + rs0;  l1 = l1 * rc1 + rs1;
        m0 = mn0;  m1 = mn1;
#pragma unroll
        for (int f = 0; f < 8; f++){
            oacc[f][0] *= rc0; oacc[f][1] *= rc0;
            oacc[f][2] *= rc1; oacc[f][3] *= rc1;
        }

        // ---- P @ V ----
#pragma unroll
        for (int kk = 0; kk < 4; kk++){
            uint32_t pah[4], pal[4];
            pah[0] = packsplit(sacc[2*kk][0],   sacc[2*kk][1],   pal[0]);
            pah[1] = packsplit(sacc[2*kk][2],   sacc[2*kk][3],   pal[1]);
            pah[2] = packsplit(sacc[2*kk+1][0], sacc[2*kk+1][1], pal[2]);
            pah[3] = packsplit(sacc[2*kk+1][2], sacc[2*kk+1][3], pal[3]);
#pragma unroll
            for (int j2 = 0; j2 < 4; j2++){
                uint32_t vd = (uint32_t)((kk*16 + ((lane >> 3) & 1)*8 + (lane & 7)) * RWB
                                         + (j2*16 + (lane >> 4)*8) * 2);
                uint32_t vh0,vh1,vh2,vh3, vl0,vl1,vl2,vl3;
                ldsm_x4t(vh0,vh1,vh2,vh3, sb + BVH + vd);
                ldsm_x4t(vl0,vl1,vl2,vl3, sb + BVL + vd);
                mma16816(oacc[2*j2],   pah[0],pah[1],pah[2],pah[3], vh0, vh1);
                mma16816(oacc[2*j2],   pah[0],pah[1],pah[2],pah[3], vl0, vl1);
                mma16816(oacc[2*j2],   pal[0],pal[1],pal[2],pal[3], vh0, vh1);
                mma16816(oacc[2*j2+1], pah[0],pah[1],pah[2],pah[3], vh2, vh3);
                mma16816(oacc[2*j2+1], pah[0],pah[1],pah[2],pah[3], vl2, vl3);
                mma16816(oacc[2*j2+1], pal[0],pal[1],pal[2],pal[3], vh2, vh3);
            }
        }
    }

    // ---- epilogue: normalize + split bf16 store ----
    float il0 = 1.f / l0, il1 = 1.f / l1;
    const int col = h*64 + 2*(lane & 3);
    size_t rowlo = (tok0 + ilo) * DM;
    size_t rowhi = (tok0 + ihi) * DM;
#pragma unroll
    for (int f = 0; f < 8; f++){
        uint32_t lo0, hi0, lo1, hi1;
        hi0 = packsplit(oacc[f][0]*il0, oacc[f][1]*il0, lo0);
        hi1 = packsplit(oacc[f][2]*il1, oacc[f][3]*il1, lo1);
        *(uint32_t*)(oh + rowlo + col + f*8) = hi0;
        *(uint32_t*)(ol + rowlo + col + f*8) = lo0;
        *(uint32_t*)(oh + rowhi + col + f*8) = hi1;
        *(uint32_t*)(ol + rowhi + col + f*8) = lo1;
    }
}

// ---------------------------------------------------------------------------
extern "C" void kernel_launch(void* const* d_in, const int* in_sizes, int n_in,
                              void* d_out, int out_size)
{
    const float* x    = (const float*)d_in[0];
    const float* Wqkv = (const float*)d_in[1];
    const float* Wout = (const float*)d_in[2];
    float* out = (float*)d_out;

    __nv_bfloat16 *xh, *xl, *wqh, *wql, *woh, *wol, *qkvh, *qkvl, *ah, *al;
    cudaGetSymbolAddress((void**)&xh, g_xh);
    cudaGetSymbolAddress((void**)&xl, g_xl);
    cudaGetSymbolAddress((void**)&wqh, g_wqT_h);
    cudaGetSymbolAddress((void**)&wql, g_wqT_l);
    cudaGetSymbolAddress((void**)&woh, g_woT_h);
    cudaGetSymbolAddress((void**)&wol, g_woT_l);
    cudaGetSymbolAddress((void**)&qkvh, g_qkvh);
    cudaGetSymbolAddress((void**)&qkvl, g_qkvl);
    cudaGetSymbolAddress((void**)&ah, g_ah);
    cudaGetSymbolAddress((void**)&al, g_al);

    cudaFuncSetAttribute(gemm_bf16x3, cudaFuncAttributeMaxDynamicSharedMemorySize, GEMM_SMEM);
    cudaFuncSetAttribute(attn_hmma, cudaFuncAttributeMaxDynamicSharedMemorySize, ATTN_SMEM);

    // 1) split x into bf16 hi/lo
    fsplit<<<(MT*DM/2 + 255)/256, 256>>>(x, xh, xl, MT*DM);
    // 2) transpose + split weights
    tsplit<<<dim3(3*DM/32, DM/32), 256>>>(Wqkv, wqh, wql, DM, 3*DM);
    tsplit<<<dim3(DM/32, DM/32), 256>>>(Wout, woh, wol, DM, DM);
    // 3) QKV projection -> split bf16 qkv
    gemm_bf16x3<<<dim3(3*DM/BN, MT/BM), 256, GEMM_SMEM>>>(xh, xl, wqh, wql,
                                                          qkvh, qkvl, nullptr, MT, 3*DM, DM);
    // 4) HMMA sliding-window attention -> split bf16 output
    attn_hmma<<<dim3(S_/64, B_*NH), 128, ATTN_SMEM>>>(qkvh, qkvl, ah, al);
    // 5) output projection -> fp32 out
    gemm_bf16x3<<<dim3(DM/BN, MT/BM), 256, GEMM_SMEM>>>(ah, al, woh, wol,
                                                        nullptr, nullptr, out, MT, DM, DM);
}

// round 5
// speedup vs baseline: 2.7238x; 1.0946x over previous
#include <cuda_runtime.h>
#include <cuda_bf16.h>
#include <math.h>
#include <stdint.h>

#define B_   2
#define S_   2048
#define DM   1024
#define NH   16
#define DH   64
#define WIN  256
#define SCALEF 0.125f
#define MT   (B_*S_)

// ---------------- scratch (__device__ globals; no allocs allowed) ----------
__device__ __nv_bfloat16 g_xh[(size_t)MT * DM],  g_xl[(size_t)MT * DM];
__device__ __nv_bfloat16 g_wqT_h[(size_t)3*DM*DM], g_wqT_l[(size_t)3*DM*DM];
__device__ __nv_bfloat16 g_woT_h[(size_t)DM*DM],   g_woT_l[(size_t)DM*DM];
__device__ __nv_bfloat16 g_qkvh[(size_t)MT*3*DM], g_qkvl[(size_t)MT*3*DM];
__device__ __nv_bfloat16 g_ah[(size_t)MT*DM],  g_al[(size_t)MT*DM];

// ---------------- helpers ---------------------------------------------------
__device__ __forceinline__ uint32_t s2u(const void* p){
    uint32_t a;
    asm("{ .reg .u64 t; cvta.to.shared.u64 t, %1; cvt.u32.u64 %0, t; }":"=r"(a):"l"(p));
    return a;
}
__device__ __forceinline__ void cp16(uint32_t dst, const void* src){
    asm volatile("cp.async.cg.shared.global [%0], [%1], 16;"::"r"(dst),"l"(src));
}
__device__ __forceinline__ void ldsm_x4(uint32_t& r0,uint32_t& r1,uint32_t& r2,uint32_t& r3,uint32_t addr){
    asm volatile("ldmatrix.sync.aligned.m8n8.x4.shared.b16 {%0,%1,%2,%3}, [%4];"
        : "=r"(r0),"=r"(r1),"=r"(r2),"=r"(r3) : "r"(addr));
}
__device__ __forceinline__ void ldsm_x4t(uint32_t& r0,uint32_t& r1,uint32_t& r2,uint32_t& r3,uint32_t addr){
    asm volatile("ldmatrix.sync.aligned.m8n8.x4.trans.shared.b16 {%0,%1,%2,%3}, [%4];"
        : "=r"(r0),"=r"(r1),"=r"(r2),"=r"(r3) : "r"(addr));
}
__device__ __forceinline__ void mma16816(float* c, uint32_t a0,uint32_t a1,uint32_t a2,uint32_t a3,
                                         uint32_t b0,uint32_t b1){
    asm volatile("mma.sync.aligned.m16n8k16.row.col.f32.bf16.bf16.f32 "
        "{%0,%1,%2,%3}, {%4,%5,%6,%7}, {%8,%9}, {%0,%1,%2,%3};"
        : "+f"(c[0]),"+f"(c[1]),"+f"(c[2]),"+f"(c[3])
        : "r"(a0),"r"(a1),"r"(a2),"r"(a3),"r"(b0),"r"(b1));
}
__device__ __forceinline__ uint32_t packsplit(float x, float y, uint32_t& lo){
    __nv_bfloat16 hx = __float2bfloat16(x), hy = __float2bfloat16(y);
    __nv_bfloat16 lx = __float2bfloat16(x - __bfloat162float(hx));
    __nv_bfloat16 ly = __float2bfloat16(y - __bfloat162float(hy));
    lo = (uint32_t)__bfloat16_as_ushort(lx) | ((uint32_t)__bfloat16_as_ushort(ly)<<16);
    return (uint32_t)__bfloat16_as_ushort(hx) | ((uint32_t)__bfloat16_as_ushort(hy)<<16);
}

// ---------------- prep kernels ---------------------------------------------
__global__ __launch_bounds__(256) void fsplit(const float* __restrict__ in,
                                              __nv_bfloat16* __restrict__ hi,
                                              __nv_bfloat16* __restrict__ lo, int n)
{
    int i = (blockIdx.x*256 + threadIdx.x)*2;
    if (i >= n) return;
    float2 v = *(const float2*)(in + i);
    __nv_bfloat16 h0 = __float2bfloat16(v.x);
    __nv_bfloat16 h1 = __float2bfloat16(v.y);
    float l0 = v.x - __bfloat162float(h0);
    float l1 = v.y - __bfloat162float(h1);
    *(__nv_bfloat162*)(hi + i) = __halves2bfloat162(h0, h1);
    *(__nv_bfloat162*)(lo + i) = __halves2bfloat162(__float2bfloat16(l0), __float2bfloat16(l1));
}

// W [K,N] row-major -> transposed split Th/Tl [N,K] bf16
__global__ __launch_bounds__(256) void tsplit(const float* __restrict__ W,
                                              __nv_bfloat16* __restrict__ Th,
                                              __nv_bfloat16* __restrict__ Tl, int K, int N)
{
    __shared__ float t[32][33];
    int n0 = blockIdx.x*32, k0 = blockIdx.y*32;
    int tx = threadIdx.x & 31, ty = threadIdx.x >> 5;  // 32x8
#pragma unroll
    for (int i = 0; i < 32; i += 8)
        t[ty+i][tx] = W[(size_t)(k0+ty+i)*N + n0+tx];
    __syncthreads();
#pragma unroll
    for (int i = 0; i < 32; i += 8){
        float v = t[tx][ty+i];
        __nv_bfloat16 h = __float2bfloat16(v);
        float lo = v - __bfloat162float(h);
        size_t o = (size_t)(n0+ty+i)*K + k0+tx;
        Th[o] = h; Tl[o] = __float2bfloat16(lo);
    }
}

// ---------------- bf16x3 HMMA GEMM ------------------------------------------
// C = Ah@Bh^T + Ah@Bl^T + Al@Bh^T.  Output: split bf16 (Ch,Cl) or fp32 (Cf).
// 2-stage cp.async pipeline, 2 CTAs/SM.
#define BM 128
#define BN 128
#define BK 32
#define ROWB 80
#define HALF_BYTES (128*ROWB)
#define GSTAGE_BYTES (4*HALF_BYTES)
#define OFF_AH 0
#define OFF_AL HALF_BYTES
#define OFF_BH (2*HALF_BYTES)
#define OFF_BL (3*HALF_BYTES)
#define GEMM_SMEM (2*GSTAGE_BYTES)

__global__ __launch_bounds__(256, 2) void gemm_bf16x3(
    const __nv_bfloat16* __restrict__ Ah, const __nv_bfloat16* __restrict__ Al,
    const __nv_bfloat16* __restrict__ Bh, const __nv_bfloat16* __restrict__ Bl,
    __nv_bfloat16* __restrict__ Ch, __nv_bfloat16* __restrict__ Cl,
    float* __restrict__ Cf, int M, int N, int K)
{
    extern __shared__ char smraw[];
    const uint32_t sb = s2u(smraw);
    const int tid = threadIdx.x, lane = tid & 31, wid = tid >> 5;
    const int row0 = blockIdx.y * BM, col0 = blockIdx.x * BN;
    const int wm = (wid & 1) * 64;
    const int wn = (wid >> 1) * 32;
    const int nch = K / BK;

    const __nv_bfloat16* pAh = Ah + (size_t)row0 * K;
    const __nv_bfloat16* pAl = Al + (size_t)row0 * K;
    const __nv_bfloat16* pBh = Bh + (size_t)col0 * K;
    const __nv_bfloat16* pBl = Bl + (size_t)col0 * K;

    const int lr = tid >> 2;
    const int lq = tid & 3;

    float acc[4][4][4];
#pragma unroll
    for (int f = 0; f < 4; f++)
#pragma unroll
        for (int j = 0; j < 4; j++)
#pragma unroll
            for (int i = 0; i < 4; i++) acc[f][j][i] = 0.f;

#define LOAD_STAGE(s_, c_)                                              \
    {                                                                   \
        uint32_t base_ = sb + (s_) * GSTAGE_BYTES;                      \
        size_t kof_ = (size_t)(c_) * BK;                                \
        _Pragma("unroll")                                               \
        for (int u = 0; u < 2; u++){                                    \
            int r_ = lr + u * 64;                                       \
            uint32_t d_ = base_ + r_ * ROWB + lq * 16;                  \
            size_t g_ = (size_t)r_ * K + kof_ + lq * 8;                 \
            cp16(d_ + OFF_AH, pAh + g_);                                \
            cp16(d_ + OFF_AL, pAl + g_);                                \
            cp16(d_ + OFF_BH, pBh + g_);                                \
            cp16(d_ + OFF_BL, pBl + g_);                                \
        }                                                               \
    }

    LOAD_STAGE(0, 0);
    asm volatile("cp.async.commit_group;");

    for (int c = 0; c < nch; c++){
        if (c + 1 < nch){
            LOAD_STAGE((c + 1) & 1, c + 1);
            asm volatile("cp.async.commit_group;");
            asm volatile("cp.async.wait_group 1;");
        } else {
            asm volatile("cp.async.wait_group 0;");
        }
        __syncthreads();

        const uint32_t base = sb + (c & 1) * GSTAGE_BYTES;
#pragma unroll
        for (int ks = 0; ks < 2; ks++){
            const uint32_t kcol = (ks * 16 + (lane >> 4) * 8) * 2;
            uint32_t ah[4][4], al[4][4], bh[2][4], bl[2][4];
#pragma unroll
            for (int f = 0; f < 4; f++){
                uint32_t ad = (wm + f * 16 + (lane & 15)) * ROWB + kcol;
                ldsm_x4(ah[f][0], ah[f][1], ah[f][2], ah[f][3], base + OFF_AH + ad);
                ldsm_x4(al[f][0], al[f][1], al[f][2], al[f][3], base + OFF_AL + ad);
            }
#pragma unroll
            for (int g = 0; g < 2; g++){
                uint32_t bd = (wn + g * 16 + (lane & 15)) * ROWB + kcol;
                ldsm_x4(bh[g][0], bh[g][1], bh[g][2], bh[g][3], base + OFF_BH + bd);
                ldsm_x4(bl[g][0], bl[g][1], bl[g][2], bl[g][3], base + OFF_BL + bd);
            }
#pragma unroll
            for (int f = 0; f < 4; f++)
#pragma unroll
                for (int j = 0; j < 4; j++){
                    const int g = j >> 1, o = j & 1;
                    mma16816(acc[f][j], ah[f][0], ah[f][1], ah[f][2], ah[f][3],
                             bh[g][o], bh[g][o + 2]);
                    mma16816(acc[f][j], ah[f][0], ah[f][1], ah[f][2], ah[f][3],
                             bl[g][o], bl[g][o + 2]);
                    mma16816(acc[f][j], al[f][0], al[f][1], al[f][2], al[f][3],
                             bh[g][o], bh[g][o + 2]);
                }
        }
        __syncthreads();
    }

#pragma unroll
    for (int f = 0; f < 4; f++){
        const int row = row0 + wm + f * 16 + (lane >> 2);
#pragma unroll
        for (int j = 0; j < 4; j++){
            const int col = col0 + wn + j * 8 + (lane & 3) * 2;
            if (Cf){
                *(float2*)(Cf + (size_t)row * N + col)       = make_float2(acc[f][j][0], acc[f][j][1]);
                *(float2*)(Cf + (size_t)(row + 8) * N + col) = make_float2(acc[f][j][2], acc[f][j][3]);
            } else {
                uint32_t lo0, hi0, lo1, hi1;
                hi0 = packsplit(acc[f][j][0], acc[f][j][1], lo0);
                hi1 = packsplit(acc[f][j][2], acc[f][j][3], lo1);
                *(uint32_t*)(Ch + (size_t)row * N + col)       = hi0;
                *(uint32_t*)(Cl + (size_t)row * N + col)       = lo0;
                *(uint32_t*)(Ch + (size_t)(row + 8) * N + col) = hi1;
                *(uint32_t*)(Cl + (size_t)(row + 8) * N + col) = lo1;
            }
        }
    }
}

// ---------------- HMMA sliding-window flash attention -----------------------
#define RWB 144
#define BQH 0
#define BQL (64*RWB)
#define BKH (2*64*RWB)
#define BKL (3*64*RWB)
#define BVH (4*64*RWB)
#define BVL (5*64*RWB)
#define ATTN_SMEM (6*64*RWB)

__global__ __launch_bounds__(128) void attn_hmma(
    const __nv_bfloat16* __restrict__ qh, const __nv_bfloat16* __restrict__ ql,
    __nv_bfloat16* __restrict__ oh, __nv_bfloat16* __restrict__ ol)
{
    extern __shared__ char smc[];
    const uint32_t sb = s2u(smc);
    const int tid = threadIdx.x, lane = tid & 31, wid = tid >> 5;
    const int qt = blockIdx.x, bhid = blockIdx.y;
    const int b = bhid >> 4, h = bhid & 15;
    const int qs = qt * 64;
    const int wm = wid * 16;
    const size_t tok0 = (size_t)b * S_;

    {
        const __nv_bfloat16* qbh = qh + (tok0 + qs) * 3072 + h * 64;
        const __nv_bfloat16* qbl = ql + (tok0 + qs) * 3072 + h * 64;
        for (int i = tid; i < 512; i += 128){
            int r = i >> 3, q = i & 7;
            *(uint4*)(smc + BQH + r*RWB + q*16) = *(const uint4*)(qbh + (size_t)r*3072 + q*8);
            *(uint4*)(smc + BQL + r*RWB + q*16) = *(const uint4*)(qbl + (size_t)r*3072 + q*8);
        }
    }
    __syncthreads();

    uint32_t aqh[4][4], aql[4][4];
#pragma unroll
    for (int ks = 0; ks < 4; ks++){
        uint32_t ad = (uint32_t)((wm + (lane & 15)) * RWB + (ks*16 + (lane >> 4)*8) * 2);
        ldsm_x4(aqh[ks][0], aqh[ks][1], aqh[ks][2], aqh[ks][3], sb + BQH + ad);
        ldsm_x4(aql[ks][0], aql[ks][1], aql[ks][2], aql[ks][3], sb + BQL + ad);
    }

    float oacc[8][4];
#pragma unroll
    for (int f = 0; f < 8; f++)
#pragma unroll
        for (int e = 0; e < 4; e++) oacc[f][e] = 0.f;
    float m0 = -1e30f, m1 = -1e30f, l0 = 0.f, l1 = 0.f;

    const int ilo = qs + wm + (lane >> 2);
    const int ihi = ilo + 8;

    const int js = qs - (WIN - 1);
    const int t0 = js > 0 ? (js >> 6) : 0;

    for (int kt = t0; kt <= qt; kt++){
        const int jb = kt * 64;
        __syncthreads();
        for (int i = tid; i < 512; i += 128){
            int r = i >> 3, q = i & 7;
            size_t g = (tok0 + jb + r) * 3072 + h*64 + q*8;
            uint32_t so = r*RWB + q*16;
            *(uint4*)(smc + BKH + so) = *(const uint4*)(qh + g + 1024);
            *(uint4*)(smc + BKL + so) = *(const uint4*)(ql + g + 1024);
            *(uint4*)(smc + BVH + so) = *(const uint4*)(qh + g + 2048);
            *(uint4*)(smc + BVL + so) = *(const uint4*)(ql + g + 2048);
        }
        __syncthreads();

        float sacc[8][4];
#pragma unroll
        for (int f = 0; f < 8; f++)
#pragma unroll
            for (int e = 0; e < 4; e++) sacc[f][e] = 0.f;

#pragma unroll
        for (int g = 0; g < 4; g++){
#pragma unroll
            for (int ks = 0; ks < 4; ks++){
                uint32_t bd = (uint32_t)((g*16 + (lane & 15)) * RWB + (ks*16 + (lane >> 4)*8) * 2);
                uint32_t kh0,kh1,kh2,kh3, kl0,kl1,kl2,kl3;
                ldsm_x4(kh0,kh1,kh2,kh3, sb + BKH + bd);
                ldsm_x4(kl0,kl1,kl2,kl3, sb + BKL + bd);
                mma16816(sacc[2*g],   aqh[ks][0],aqh[ks][1],aqh[ks][2],aqh[ks][3], kh0, kh2);
                mma16816(sacc[2*g],   aqh[ks][0],aqh[ks][1],aqh[ks][2],aqh[ks][3], kl0, kl2);
                mma16816(sacc[2*g],   aql[ks][0],aql[ks][1],aql[ks][2],aql[ks][3], kh0, kh2);
                mma16816(sacc[2*g+1], aqh[ks][0],aqh[ks][1],aqh[ks][2],aqh[ks][3], kh1, kh3);
                mma16816(sacc[2*g+1], aqh[ks][0],aqh[ks][1],aqh[ks][2],aqh[ks][3], kl1, kl3);
                mma16816(sacc[2*g+1], aql[ks][0],aql[ks][1],aql[ks][2],aql[ks][3], kh1, kh3);
            }
        }

        float mx0 = -1e30f, mx1 = -1e30f;
#pragma unroll
        for (int f = 0; f < 8; f++){
            int c0 = jb + f*8 + 2*(lane & 3);
            int c1 = c0 + 1;
            float s0 = sacc[f][0]*SCALEF, s1 = sacc[f][1]*SCALEF;
            float s2 = sacc[f][2]*SCALEF, s3 = sacc[f][3]*SCALEF;
            sacc[f][0] = (c0 <= ilo && c0 > ilo - WIN) ? s0 : -1e30f;
            sacc[f][1] = (c1 <= ilo && c1 > ilo - WIN) ? s1 : -1e30f;
            sacc[f][2] = (c0 <= ihi && c0 > ihi - WIN) ? s2 : -1e30f;
            sacc[f][3] = (c1 <= ihi && c1 > ihi - WIN) ? s3 : -1e30f;
            mx0 = fmaxf(mx0, fmaxf(sacc[f][0], sacc[f][1]));
            mx1 = fmaxf(mx1, fmaxf(sacc[f][2], sacc[f][3]));
        }
        mx0 = fmaxf(mx0, __shfl_xor_sync(0xffffffffu, mx0, 1));
        mx0 = fmaxf(mx0, __shfl_xor_sync(0xffffffffu, mx0, 2));
        mx1 = fmaxf(mx1, __shfl_xor_sync(0xffffffffu, mx1, 1));
        mx1 = fmaxf(mx1, __shfl_xor_sync(0xffffffffu, mx1, 2));
        float mn0 = fmaxf(m0, mx0), mn1 = fmaxf(m1, mx1);
        float rc0 = __expf(m0 - mn0), rc1 = __expf(m1 - mn1);
        float rs0 = 0.f, rs1 = 0.f;
#pragma unroll
        for (int f = 0; f < 8; f++){
            sacc[f][0] = __expf(sacc[f][0] - mn0);
            sacc[f][1] = __expf(sacc[f][1] - mn0);
            sacc[f][2] = __expf(sacc[f][2] - mn1);
            sacc[f][3] = __expf(sacc[f][3] - mn1);
            rs0 += sacc[f][0] + sacc[f][1];
            rs1 += sacc[f][2] + sacc[f][3];
        }
        rs0 += __shfl_xor_sync(0xffffffffu, rs0, 1);
        rs0 += __shfl_xor_sync(0xffffffffu, rs0, 2);
        rs1 += __shfl_xor_sync(0xffffffffu, rs1, 1);
        rs1 += __shfl_xor_sync(0xffffffffu, rs1, 2);
        l0 = l0 * rc0 + rs0;  l1 = l1 * rc1 + rs1;
        m0 = mn0;  m1 = mn1;
#pragma unroll
        for (int f = 0; f < 8; f++){
            oacc[f][0] *= rc0; oacc[f][1] *= rc0;
            oacc[f][2] *= rc1; oacc[f][3] *= rc1;
        }

#pragma unroll
        for (int kk = 0; kk < 4; kk++){
            uint32_t pah[4], pal[4];
            pah[0] = packsplit(sacc[2*kk][0],   sacc[2*kk][1],   pal[0]);
            pah[1] = packsplit(sacc[2*kk][2],   sacc[2*kk][3],   pal[1]);
            pah[2] = packsplit(sacc[2*kk+1][0], sacc[2*kk+1][1], pal[2]);
            pah[3] = packsplit(sacc[2*kk+1][2], sacc[2*kk+1][3], pal[3]);
#pragma unroll
            for (int j2 = 0; j2 < 4; j2++){
                uint32_t vd = (uint32_t)((kk*16 + ((lane >> 3) & 1)*8 + (lane & 7)) * RWB
                                         + (j2*16 + (lane >> 4)*8) * 2);
                uint32_t vh0,vh1,vh2,vh3, vl0,vl1,vl2,vl3;
                ldsm_x4t(vh0,vh1,vh2,vh3, sb + BVH + vd);
                ldsm_x4t(vl0,vl1,vl2,vl3, sb + BVL + vd);
                mma16816(oacc[2*j2],   pah[0],pah[1],pah[2],pah[3], vh0, vh1);
                mma16816(oacc[2*j2],   pah[0],pah[1],pah[2],pah[3], vl0, vl1);
                mma16816(oacc[2*j2],   pal[0],pal[1],pal[2],pal[3], vh0, vh1);
                mma16816(oacc[2*j2+1], pah[0],pah[1],pah[2],pah[3], vh2, vh3);
                mma16816(oacc[2*j2+1], pah[0],pah[1],pah[2],pah[3], vl2, vl3);
                mma16816(oacc[2*j2+1], pal[0],pal[1],pal[2],pal[3], vh2, vh3);
            }
        }
    }

    float il0 = 1.f / l0, il1 = 1.f / l1;
    const int col = h*64 + 2*(lane & 3);
    size_t rowlo = (tok0 + ilo) * DM;
    size_t rowhi = (tok0 + ihi) * DM;
#pragma unroll
    for (int f = 0; f < 8; f++){
        uint32_t lo0, hi0, lo1, hi1;
        hi0 = packsplit(oacc[f][0]*il0, oacc[f][1]*il0, lo0);
        hi1 = packsplit(oacc[f][2]*il1, oacc[f][3]*il1, lo1);
        *(uint32_t*)(oh + rowlo + col + f*8) = hi0;
        *(uint32_t*)(ol + rowlo + col + f*8) = lo0;
        *(uint32_t*)(oh + rowhi + col + f*8) = hi1;
        *(uint32_t*)(ol + rowhi + col + f*8) = lo1;
    }
}

// ---------------------------------------------------------------------------
extern "C" void kernel_launch(void* const* d_in, const int* in_sizes, int n_in,
                              void* d_out, int out_size)
{
    const float* x    = (const float*)d_in[0];
    const float* Wqkv = (const float*)d_in[1];
    const float* Wout = (const float*)d_in[2];
    float* out = (float*)d_out;

    __nv_bfloat16 *xh, *xl, *wqh, *wql, *woh, *wol, *qkvh, *qkvl, *ah, *al;
    cudaGetSymbolAddress((void**)&xh, g_xh);
    cudaGetSymbolAddress((void**)&xl, g_xl);
    cudaGetSymbolAddress((void**)&wqh, g_wqT_h);
    cudaGetSymbolAddress((void**)&wql, g_wqT_l);
    cudaGetSymbolAddress((void**)&woh, g_woT_h);
    cudaGetSymbolAddress((void**)&wol, g_woT_l);
    cudaGetSymbolAddress((void**)&qkvh, g_qkvh);
    cudaGetSymbolAddress((void**)&qkvl, g_qkvl);
    cudaGetSymbolAddress((void**)&ah, g_ah);
    cudaGetSymbolAddress((void**)&al, g_al);

    cudaFuncSetAttribute(gemm_bf16x3, cudaFuncAttributeMaxDynamicSharedMemorySize, GEMM_SMEM);
    cudaFuncSetAttribute(attn_hmma, cudaFuncAttributeMaxDynamicSharedMemorySize, ATTN_SMEM);

    fsplit<<<(MT*DM/2 + 255)/256, 256>>>(x, xh, xl, MT*DM);
    tsplit<<<dim3(3*DM/32, DM/32), 256>>>(Wqkv, wqh, wql, DM, 3*DM);
    tsplit<<<dim3(DM/32, DM/32), 256>>>(Wout, woh, wol, DM, DM);
    gemm_bf16x3<<<dim3(3*DM/BN, MT/BM), 256, GEMM_SMEM>>>(xh, xl, wqh, wql,
                                                          qkvh, qkvl, nullptr, MT, 3*DM, DM);
    attn_hmma<<<dim3(S_/64, B_*NH), 128, ATTN_SMEM>>>(qkvh, qkvl, ah, al);
    gemm_bf16x3<<<dim3(DM/BN, MT/BM), 256, GEMM_SMEM>>>(ah, al, woh, wol,
                                                        nullptr, nullptr, out, MT, DM, DM);
}

// round 6
// speedup vs baseline: 2.7835x; 1.0219x over previous
#include <cuda_runtime.h>
#include <cuda_bf16.h>
#include <math.h>
#include <stdint.h>

#define B_   2
#define S_   2048
#define DM   1024
#define NH   16
#define DH   64
#define WIN  256
#define SCALEF 0.125f
#define MT   (B_*S_)

// ---------------- scratch (__device__ globals; no allocs allowed) ----------
__device__ __nv_bfloat16 g_xh[(size_t)MT * DM],  g_xl[(size_t)MT * DM];
__device__ __nv_bfloat16 g_wqT_h[(size_t)3*DM*DM], g_wqT_l[(size_t)3*DM*DM];
__device__ __nv_bfloat16 g_woT_h[(size_t)DM*DM],   g_woT_l[(size_t)DM*DM];
__device__ __nv_bfloat16 g_qkvh[(size_t)MT*3*DM], g_qkvl[(size_t)MT*3*DM];
__device__ __nv_bfloat16 g_ah[(size_t)MT*DM],  g_al[(size_t)MT*DM];

// ---------------- helpers ---------------------------------------------------
__device__ __forceinline__ uint32_t s2u(const void* p){
    uint32_t a;
    asm("{ .reg .u64 t; cvta.to.shared.u64 t, %1; cvt.u32.u64 %0, t; }":"=r"(a):"l"(p));
    return a;
}
__device__ __forceinline__ void cp16(uint32_t dst, const void* src){
    asm volatile("cp.async.cg.shared.global [%0], [%1], 16;"::"r"(dst),"l"(src));
}
__device__ __forceinline__ void ldsm_x4(uint32_t& r0,uint32_t& r1,uint32_t& r2,uint32_t& r3,uint32_t addr){
    asm volatile("ldmatrix.sync.aligned.m8n8.x4.shared.b16 {%0,%1,%2,%3}, [%4];"
        : "=r"(r0),"=r"(r1),"=r"(r2),"=r"(r3) : "r"(addr));
}
__device__ __forceinline__ void ldsm_x4t(uint32_t& r0,uint32_t& r1,uint32_t& r2,uint32_t& r3,uint32_t addr){
    asm volatile("ldmatrix.sync.aligned.m8n8.x4.trans.shared.b16 {%0,%1,%2,%3}, [%4];"
        : "=r"(r0),"=r"(r1),"=r"(r2),"=r"(r3) : "r"(addr));
}
__device__ __forceinline__ void mma16816(float* c, uint32_t a0,uint32_t a1,uint32_t a2,uint32_t a3,
                                         uint32_t b0,uint32_t b1){
    asm volatile("mma.sync.aligned.m16n8k16.row.col.f32.bf16.bf16.f32 "
        "{%0,%1,%2,%3}, {%4,%5,%6,%7}, {%8,%9}, {%0,%1,%2,%3};"
        : "+f"(c[0]),"+f"(c[1]),"+f"(c[2]),"+f"(c[3])
        : "r"(a0),"r"(a1),"r"(a2),"r"(a3),"r"(b0),"r"(b1));
}
__device__ __forceinline__ uint32_t packsplit(float x, float y, uint32_t& lo){
    __nv_bfloat16 hx = __float2bfloat16(x), hy = __float2bfloat16(y);
    __nv_bfloat16 lx = __float2bfloat16(x - __bfloat162float(hx));
    __nv_bfloat16 ly = __float2bfloat16(y - __bfloat162float(hy));
    lo = (uint32_t)__bfloat16_as_ushort(lx) | ((uint32_t)__bfloat16_as_ushort(ly)<<16);
    return (uint32_t)__bfloat16_as_ushort(hx) | ((uint32_t)__bfloat16_as_ushort(hy)<<16);
}

// ---------------- prep kernels ---------------------------------------------
__global__ __launch_bounds__(256) void fsplit(const float* __restrict__ in,
                                              __nv_bfloat16* __restrict__ hi,
                                              __nv_bfloat16* __restrict__ lo, int n)
{
    int i = (blockIdx.x*256 + threadIdx.x)*2;
    if (i >= n) return;
    float2 v = *(const float2*)(in + i);
    __nv_bfloat16 h0 = __float2bfloat16(v.x);
    __nv_bfloat16 h1 = __float2bfloat16(v.y);
    float l0 = v.x - __bfloat162float(h0);
    float l1 = v.y - __bfloat162float(h1);
    *(__nv_bfloat162*)(hi + i) = __halves2bfloat162(h0, h1);
    *(__nv_bfloat162*)(lo + i) = __halves2bfloat162(__float2bfloat16(l0), __float2bfloat16(l1));
}

// W [K,N] row-major -> transposed split Th/Tl [N,K] bf16
__global__ __launch_bounds__(256) void tsplit(const float* __restrict__ W,
                                              __nv_bfloat16* __restrict__ Th,
                                              __nv_bfloat16* __restrict__ Tl, int K, int N)
{
    __shared__ float t[32][33];
    int n0 = blockIdx.x*32, k0 = blockIdx.y*32;
    int tx = threadIdx.x & 31, ty = threadIdx.x >> 5;  // 32x8
#pragma unroll
    for (int i = 0; i < 32; i += 8)
        t[ty+i][tx] = W[(size_t)(k0+ty+i)*N + n0+tx];
    __syncthreads();
#pragma unroll
    for (int i = 0; i < 32; i += 8){
        float v = t[tx][ty+i];
        __nv_bfloat16 h = __float2bfloat16(v);
        float lo = v - __bfloat162float(h);
        size_t o = (size_t)(n0+ty+i)*K + k0+tx;
        Th[o] = h; Tl[o] = __float2bfloat16(lo);
    }
}

// ---------------- bf16x3 HMMA GEMM ------------------------------------------
// C = Ah@Bh^T + Ah@Bl^T + Al@Bh^T.  Output: split bf16 (Ch,Cl) or fp32 (Cf).
// CTA tile 64x128, warp tile 32x32, 2-stage cp.async, 3 CTAs/SM target.
#define BM 64
#define BN 128
#define BK 32
#define ROWB 80
#define OFF_AH 0
#define OFF_AL (BM*ROWB)
#define OFF_BH (2*BM*ROWB)
#define OFF_BL (2*BM*ROWB + BN*ROWB)
#define GSTAGE_BYTES (2*BM*ROWB + 2*BN*ROWB)   // 30720
#define GEMM_SMEM (2*GSTAGE_BYTES)             // 61440

__global__ __launch_bounds__(256, 3) void gemm_bf16x3(
    const __nv_bfloat16* __restrict__ Ah, const __nv_bfloat16* __restrict__ Al,
    const __nv_bfloat16* __restrict__ Bh, const __nv_bfloat16* __restrict__ Bl,
    __nv_bfloat16* __restrict__ Ch, __nv_bfloat16* __restrict__ Cl,
    float* __restrict__ Cf, int M, int N, int K)
{
    extern __shared__ char smraw[];
    const uint32_t sb = s2u(smraw);
    const int tid = threadIdx.x, lane = tid & 31, wid = tid >> 5;
    const int row0 = blockIdx.y * BM, col0 = blockIdx.x * BN;
    const int wm = (wid & 1) * 32;    // 2 warps in M
    const int wn = (wid >> 1) * 32;   // 4 warps in N
    const int nch = K / BK;

    const __nv_bfloat16* pAh = Ah + (size_t)row0 * K;
    const __nv_bfloat16* pAl = Al + (size_t)row0 * K;
    const __nv_bfloat16* pBh = Bh + (size_t)col0 * K;
    const __nv_bfloat16* pBl = Bl + (size_t)col0 * K;

    const int lr = tid >> 2;    // 0..63
    const int lq = tid & 3;     // 16B chunk in 64B row

    float acc[2][4][4];
#pragma unroll
    for (int f = 0; f < 2; f++)
#pragma unroll
        for (int j = 0; j < 4; j++)
#pragma unroll
            for (int i = 0; i < 4; i++) acc[f][j][i] = 0.f;

#define LOAD_STAGE(s_, c_)                                              \
    {                                                                   \
        uint32_t base_ = sb + (s_) * GSTAGE_BYTES;                      \
        size_t kof_ = (size_t)(c_) * BK;                                \
        uint32_t d_ = base_ + lr * ROWB + lq * 16;                      \
        size_t g_ = (size_t)lr * K + kof_ + lq * 8;                     \
        size_t g2_ = (size_t)(lr + 64) * K + kof_ + lq * 8;             \
        cp16(d_ + OFF_AH, pAh + g_);                                    \
        cp16(d_ + OFF_AL, pAl + g_);                                    \
        cp16(d_ + OFF_BH, pBh + g_);                                    \
        cp16(d_ + OFF_BL, pBl + g_);                                    \
        cp16(d_ + OFF_BH + 64*ROWB, pBh + g2_);                         \
        cp16(d_ + OFF_BL + 64*ROWB, pBl + g2_);                         \
    }

    LOAD_STAGE(0, 0);
    asm volatile("cp.async.commit_group;");

    for (int c = 0; c < nch; c++){
        if (c + 1 < nch){
            LOAD_STAGE((c + 1) & 1, c + 1);
            asm volatile("cp.async.commit_group;");
            asm volatile("cp.async.wait_group 1;");
        } else {
            asm volatile("cp.async.wait_group 0;");
        }
        __syncthreads();

        const uint32_t base = sb + (c & 1) * GSTAGE_BYTES;
#pragma unroll
        for (int ks = 0; ks < 2; ks++){
            const uint32_t kcol = (ks * 16 + (lane >> 4) * 8) * 2;
            uint32_t ah[2][4], al[2][4], bh[2][4], bl[2][4];
#pragma unroll
            for (int f = 0; f < 2; f++){
                uint32_t ad = (wm + f * 16 + (lane & 15)) * ROWB + kcol;
                ldsm_x4(ah[f][0], ah[f][1], ah[f][2], ah[f][3], base + OFF_AH + ad);
                ldsm_x4(al[f][0], al[f][1], al[f][2], al[f][3], base + OFF_AL + ad);
            }
#pragma unroll
            for (int g = 0; g < 2; g++){
                uint32_t bd = (wn + g * 16 + (lane & 15)) * ROWB + kcol;
                ldsm_x4(bh[g][0], bh[g][1], bh[g][2], bh[g][3], base + OFF_BH + bd);
                ldsm_x4(bl[g][0], bl[g][1], bl[g][2], bl[g][3], base + OFF_BL + bd);
            }
#pragma unroll
            for (int f = 0; f < 2; f++)
#pragma unroll
                for (int j = 0; j < 4; j++){
                    const int g = j >> 1, o = j & 1;
                    mma16816(acc[f][j], ah[f][0], ah[f][1], ah[f][2], ah[f][3],
                             bh[g][o], bh[g][o + 2]);
                    mma16816(acc[f][j], ah[f][0], ah[f][1], ah[f][2], ah[f][3],
                             bl[g][o], bl[g][o + 2]);
                    mma16816(acc[f][j], al[f][0], al[f][1], al[f][2], al[f][3],
                             bh[g][o], bh[g][o + 2]);
                }
        }
        __syncthreads();
    }

#pragma unroll
    for (int f = 0; f < 2; f++){
        const int row = row0 + wm + f * 16 + (lane >> 2);
#pragma unroll
        for (int j = 0; j < 4; j++){
            const int col = col0 + wn + j * 8 + (lane & 3) * 2;
            if (Cf){
                *(float2*)(Cf + (size_t)row * N + col)       = make_float2(acc[f][j][0], acc[f][j][1]);
                *(float2*)(Cf + (size_t)(row + 8) * N + col) = make_float2(acc[f][j][2], acc[f][j][3]);
            } else {
                uint32_t lo0, hi0, lo1, hi1;
                hi0 = packsplit(acc[f][j][0], acc[f][j][1], lo0);
                hi1 = packsplit(acc[f][j][2], acc[f][j][3], lo1);
                *(uint32_t*)(Ch + (size_t)row * N + col)       = hi0;
                *(uint32_t*)(Cl + (size_t)row * N + col)       = lo0;
                *(uint32_t*)(Ch + (size_t)(row + 8) * N + col) = hi1;
                *(uint32_t*)(Cl + (size_t)(row + 8) * N + col) = lo1;
            }
        }
    }
}

// ---------------- HMMA sliding-window flash attention -----------------------
#define RWB 144
#define BQH 0
#define BQL (64*RWB)
#define BKH (2*64*RWB)
#define BKL (3*64*RWB)
#define BVH (4*64*RWB)
#define BVL (5*64*RWB)
#define ATTN_SMEM (6*64*RWB)

__global__ __launch_bounds__(128) void attn_hmma(
    const __nv_bfloat16* __restrict__ qh, const __nv_bfloat16* __restrict__ ql,
    __nv_bfloat16* __restrict__ oh, __nv_bfloat16* __restrict__ ol)
{
    extern __shared__ char smc[];
    const uint32_t sb = s2u(smc);
    const int tid = threadIdx.x, lane = tid & 31, wid = tid >> 5;
    const int qt = blockIdx.x, bhid = blockIdx.y;
    const int b = bhid >> 4, h = bhid & 15;
    const int qs = qt * 64;
    const int wm = wid * 16;
    const size_t tok0 = (size_t)b * S_;

    {
        const __nv_bfloat16* qbh = qh + (tok0 + qs) * 3072 + h * 64;
        const __nv_bfloat16* qbl = ql + (tok0 + qs) * 3072 + h * 64;
        for (int i = tid; i < 512; i += 128){
            int r = i >> 3, q = i & 7;
            *(uint4*)(smc + BQH + r*RWB + q*16) = *(const uint4*)(qbh + (size_t)r*3072 + q*8);
            *(uint4*)(smc + BQL + r*RWB + q*16) = *(const uint4*)(qbl + (size_t)r*3072 + q*8);
        }
    }
    __syncthreads();

    uint32_t aqh[4][4], aql[4][4];
#pragma unroll
    for (int ks = 0; ks < 4; ks++){
        uint32_t ad = (uint32_t)((wm + (lane & 15)) * RWB + (ks*16 + (lane >> 4)*8) * 2);
        ldsm_x4(aqh[ks][0], aqh[ks][1], aqh[ks][2], aqh[ks][3], sb + BQH + ad);
        ldsm_x4(aql[ks][0], aql[ks][1], aql[ks][2], aql[ks][3], sb + BQL + ad);
    }

    float oacc[8][4];
#pragma unroll
    for (int f = 0; f < 8; f++)
#pragma unroll
        for (int e = 0; e < 4; e++) oacc[f][e] = 0.f;
    float m0 = -1e30f, m1 = -1e30f, l0 = 0.f, l1 = 0.f;

    const int ilo = qs + wm + (lane >> 2);
    const int ihi = ilo + 8;

    const int js = qs - (WIN - 1);
    const int t0 = js > 0 ? (js >> 6) : 0;

    for (int kt = t0; kt <= qt; kt++){
        const int jb = kt * 64;
        __syncthreads();
        for (int i = tid; i < 512; i += 128){
            int r = i >> 3, q = i & 7;
            size_t g = (tok0 + jb + r) * 3072 + h*64 + q*8;
            uint32_t so = r*RWB + q*16;
            *(uint4*)(smc + BKH + so) = *(const uint4*)(qh + g + 1024);
            *(uint4*)(smc + BKL + so) = *(const uint4*)(ql + g + 1024);
            *(uint4*)(smc + BVH + so) = *(const uint4*)(qh + g + 2048);
            *(uint4*)(smc + BVL + so) = *(const uint4*)(ql + g + 2048);
        }
        __syncthreads();

        float sacc[8][4];
#pragma unroll
        for (int f = 0; f < 8; f++)
#pragma unroll
            for (int e = 0; e < 4; e++) sacc[f][e] = 0.f;

#pragma unroll
        for (int g = 0; g < 4; g++){
#pragma unroll
            for (int ks = 0; ks < 4; ks++){
                uint32_t bd = (uint32_t)((g*16 + (lane & 15)) * RWB + (ks*16 + (lane >> 4)*8) * 2);
                uint32_t kh0,kh1,kh2,kh3, kl0,kl1,kl2,kl3;
                ldsm_x4(kh0,kh1,kh2,kh3, sb + BKH + bd);
                ldsm_x4(kl0,kl1,kl2,kl3, sb + BKL + bd);
                mma16816(sacc[2*g],   aqh[ks][0],aqh[ks][1],aqh[ks][2],aqh[ks][3], kh0, kh2);
                mma16816(sacc[2*g],   aqh[ks][0],aqh[ks][1],aqh[ks][2],aqh[ks][3], kl0, kl2);
                mma16816(sacc[2*g],   aql[ks][0],aql[ks][1],aql[ks][2],aql[ks][3], kh0, kh2);
                mma16816(sacc[2*g+1], aqh[ks][0],aqh[ks][1],aqh[ks][2],aqh[ks][3], kh1, kh3);
                mma16816(sacc[2*g+1], aqh[ks][0],aqh[ks][1],aqh[ks][2],aqh[ks][3], kl1, kl3);
                mma16816(sacc[2*g+1], aql[ks][0],aql[ks][1],aql[ks][2],aql[ks][3], kh1, kh3);
            }
        }

        float mx0 = -1e30f, mx1 = -1e30f;
#pragma unroll
        for (int f = 0; f < 8; f++){
            int c0 = jb + f*8 + 2*(lane & 3);
            int c1 = c0 + 1;
            float s0 = sacc[f][0]*SCALEF, s1 = sacc[f][1]*SCALEF;
            float s2 = sacc[f][2]*SCALEF, s3 = sacc[f][3]*SCALEF;
            sacc[f][0] = (c0 <= ilo && c0 > ilo - WIN) ? s0 : -1e30f;
            sacc[f][1] = (c1 <= ilo && c1 > ilo - WIN) ? s1 : -1e30f;
            sacc[f][2] = (c0 <= ihi && c0 > ihi - WIN) ? s2 : -1e30f;
            sacc[f][3] = (c1 <= ihi && c1 > ihi - WIN) ? s3 : -1e30f;
            mx0 = fmaxf(mx0, fmaxf(sacc[f][0], sacc[f][1]));
            mx1 = fmaxf(mx1, fmaxf(sacc[f][2], sacc[f][3]));
        }
        mx0 = fmaxf(mx0, __shfl_xor_sync(0xffffffffu, mx0, 1));
        mx0 = fmaxf(mx0, __shfl_xor_sync(0xffffffffu, mx0, 2));
        mx1 = fmaxf(mx1, __shfl_xor_sync(0xffffffffu, mx1, 1));
        mx1 = fmaxf(mx1, __shfl_xor_sync(0xffffffffu, mx1, 2));
        float mn0 = fmaxf(m0, mx0), mn1 = fmaxf(m1, mx1);
        float rc0 = __expf(m0 - mn0), rc1 = __expf(m1 - mn1);
        float rs0 = 0.f, rs1 = 0.f;
#pragma unroll
        for (int f = 0; f < 8; f++){
            sacc[f][0] = __expf(sacc[f][0] - mn0);
            sacc[f][1] = __expf(sacc[f][1] - mn0);
            sacc[f][2] = __expf(sacc[f][2] - mn1);
            sacc[f][3] = __expf(sacc[f][3] - mn1);
            rs0 += sacc[f][0] + sacc[f][1];
            rs1 += sacc[f][2] + sacc[f][3];
        }
        rs0 += __shfl_xor_sync(0xffffffffu, rs0, 1);
        rs0 += __shfl_xor_sync(0xffffffffu, rs0, 2);
        rs1 += __shfl_xor_sync(0xffffffffu, rs1, 1);
        rs1 += __shfl_xor_sync(0xffffffffu, rs1, 2);
        l0 = l0 * rc0 + rs0;  l1 = l1 * rc1 + rs1;
        m0 = mn0;  m1 = mn1;
#pragma unroll
        for (int f = 0; f < 8; f++){
            oacc[f][0] *= rc0; oacc[f][1] *= rc0;
            oacc[f][2] *= rc1; oacc[f][3] *= rc1;
        }

#pragma unroll
        for (int kk = 0; kk < 4; kk++){
            uint32_t pah[4], pal[4];
            pah[0] = packsplit(sacc[2*kk][0],   sacc[2*kk][1],   pal[0]);
            pah[1] = packsplit(sacc[2*kk][2],   sacc[2*kk][3],   pal[1]);
            pah[2] = packsplit(sacc[2*kk+1][0], sacc[2*kk+1][1], pal[2]);
            pah[3] = packsplit(sacc[2*kk+1][2], sacc[2*kk+1][3], pal[3]);
#pragma unroll
            for (int j2 = 0; j2 < 4; j2++){
                uint32_t vd = (uint32_t)((kk*16 + ((lane >> 3) & 1)*8 + (lane & 7)) * RWB
                                         + (j2*16 + (lane >> 4)*8) * 2);
                uint32_t vh0,vh1,vh2,vh3, vl0,vl1,vl2,vl3;
                ldsm_x4t(vh0,vh1,vh2,vh3, sb + BVH + vd);
                ldsm_x4t(vl0,vl1,vl2,vl3, sb + BVL + vd);
                mma16816(oacc[2*j2],   pah[0],pah[1],pah[2],pah[3], vh0, vh1);
                mma16816(oacc[2*j2],   pah[0],pah[1],pah[2],pah[3], vl0, vl1);
                mma16816(oacc[2*j2],   pal[0],pal[1],pal[2],pal[3], vh0, vh1);
                mma16816(oacc[2*j2+1], pah[0],pah[1],pah[2],pah[3], vh2, vh3);
                mma16816(oacc[2*j2+1], pah[0],pah[1],pah[2],pah[3], vl2, vl3);
                mma16816(oacc[2*j2+1], pal[0],pal[1],pal[2],pal[3], vh2, vh3);
            }
        }
    }

    float il0 = 1.f / l0, il1 = 1.f / l1;
    const int col = h*64 + 2*(lane & 3);
    size_t rowlo = (tok0 + ilo) * DM;
    size_t rowhi = (tok0 + ihi) * DM;
#pragma unroll
    for (int f = 0; f < 8; f++){
        uint32_t lo0, hi0, lo1, hi1;
        hi0 = packsplit(oacc[f][0]*il0, oacc[f][1]*il0, lo0);
        hi1 = packsplit(oacc[f][2]*il1, oacc[f][3]*il1, lo1);
        *(uint32_t*)(oh + rowlo + col + f*8) = hi0;
        *(uint32_t*)(ol + rowlo + col + f*8) = lo0;
        *(uint32_t*)(oh + rowhi + col + f*8) = hi1;
        *(uint32_t*)(ol + rowhi + col + f*8) = lo1;
    }
}

// ---------------------------------------------------------------------------
extern "C" void kernel_launch(void* const* d_in, const int* in_sizes, int n_in,
                              void* d_out, int out_size)
{
    const float* x    = (const float*)d_in[0];
    const float* Wqkv = (const float*)d_in[1];
    const float* Wout = (const float*)d_in[2];
    float* out = (float*)d_out;

    __nv_bfloat16 *xh, *xl, *wqh, *wql, *woh, *wol, *qkvh, *qkvl, *ah, *al;
    cudaGetSymbolAddress((void**)&xh, g_xh);
    cudaGetSymbolAddress((void**)&xl, g_xl);
    cudaGetSymbolAddress((void**)&wqh, g_wqT_h);
    cudaGetSymbolAddress((void**)&wql, g_wqT_l);
    cudaGetSymbolAddress((void**)&woh, g_woT_h);
    cudaGetSymbolAddress((void**)&wol, g_woT_l);
    cudaGetSymbolAddress((void**)&qkvh, g_qkvh);
    cudaGetSymbolAddress((void**)&qkvl, g_qkvl);
    cudaGetSymbolAddress((void**)&ah, g_ah);
    cudaGetSymbolAddress((void**)&al, g_al);

    cudaFuncSetAttribute(gemm_bf16x3, cudaFuncAttributeMaxDynamicSharedMemorySize, GEMM_SMEM);
    cudaFuncSetAttribute(attn_hmma, cudaFuncAttributeMaxDynamicSharedMemorySize, ATTN_SMEM);

    fsplit<<<(MT*DM/2 + 255)/256, 256>>>(x, xh, xl, MT*DM);
    tsplit<<<dim3(3*DM/32, DM/32), 256>>>(Wqkv, wqh, wql, DM, 3*DM);
    tsplit<<<dim3(DM/32, DM/32), 256>>>(Wout, woh, wol, DM, DM);
    gemm_bf16x3<<<dim3(3*DM/BN, MT/BM), 256, GEMM_SMEM>>>(xh, xl, wqh, wql,
                                                          qkvh, qkvl, nullptr, MT, 3*DM, DM);
    attn_hmma<<<dim3(S_/64, B_*NH), 128, ATTN_SMEM>>>(qkvh, qkvl, ah, al);
    gemm_bf16x3<<<dim3(DM/BN, MT/BM), 256, GEMM_SMEM>>>(ah, al, woh, wol,
                                                        nullptr, nullptr, out, MT, DM, DM);
}